// round 1
// baseline (speedup 1.0000x reference)
#include <cuda_runtime.h>
#include <cuda_bf16.h>

// Problem constants
#define N_ROWS   32768
#define D_IN     256
#define D_HID    1024
#define D_OUT    256
#define N_DOM    8
#define LN_EPS   1e-5f

// GEMM tiling
#define BM 128
#define BN 128
#define BK 8
#define TM 8
#define TN 8
#define NTHREADS 256

#define MAX_TILES 384   // sum_d ceil(count_d/128) <= 256 + 7

// ---------------- device scratch (no allocation allowed) ----------------
__device__ int g_count[N_DOM];
__device__ int g_offset[N_DOM];
__device__ int g_fill[N_DOM];
__device__ int g_perm[N_ROWS];          // gathered index -> original row
__device__ int g_tile_dom[MAX_TILES];
__device__ int g_tile_row[MAX_TILES];   // start (gathered order)
__device__ int g_tile_cnt[MAX_TILES];
__device__ int g_ntiles;
__device__ __align__(16) float g_h[(size_t)N_ROWS * D_HID]; // 128 MiB intermediate

// ---------------- sort/plan kernels ----------------
__global__ void init_kernel() {
    int t = threadIdx.x;
    if (t < N_DOM) { g_count[t] = 0; g_fill[t] = 0; }
}

__global__ void hist_kernel(const int* __restrict__ dom) {
    int i = blockIdx.x * blockDim.x + threadIdx.x;
    if (i < N_ROWS) atomicAdd(&g_count[dom[i]], 1);
}

__global__ void plan_kernel() {
    if (threadIdx.x == 0 && blockIdx.x == 0) {
        int off = 0, nt = 0;
        for (int d = 0; d < N_DOM; d++) {
            g_offset[d] = off;
            int c = g_count[d];
            for (int t = 0; t < c; t += BM) {
                g_tile_dom[nt] = d;
                g_tile_row[nt] = off + t;
                g_tile_cnt[nt] = min(BM, c - t);
                nt++;
            }
            off += c;
        }
        g_ntiles = nt;
    }
}

__global__ void scatter_kernel(const int* __restrict__ dom) {
    int i = blockIdx.x * blockDim.x + threadIdx.x;
    if (i < N_ROWS) {
        int d = dom[i];
        int pos = g_offset[d] + atomicAdd(&g_fill[d], 1);
        g_perm[pos] = i;
    }
}

// ---------------- GEMM1: h = gather(x) @ W1[d] + b1[d] ----------------
__global__ __launch_bounds__(NTHREADS)
void gemm1_kernel(const float* __restrict__ x,
                  const float* __restrict__ W1,
                  const float* __restrict__ b1) {
    int bt = blockIdx.x;
    if (bt >= g_ntiles) return;
    int dom  = g_tile_dom[bt];
    int row0 = g_tile_row[bt];
    int cnt  = g_tile_cnt[bt];
    int colBase = blockIdx.y * BN;

    const float* B = W1 + (size_t)dom * D_IN * D_HID;

    __shared__ float As[BK][BM];
    __shared__ float Bs[BK][BN];

    int tid = threadIdx.x;
    int tr = (tid / 16) * TM;
    int tc = (tid % 16) * TN;

    float acc[TM][TN];
    #pragma unroll
    for (int i = 0; i < TM; i++)
        #pragma unroll
        for (int j = 0; j < TN; j++) acc[i][j] = 0.f;

    // A loads: 128 rows x 8 cols = 256 float4
    int arow = tid >> 1;
    int acol = (tid & 1) * 4;
    int srcRow = (arow < cnt) ? g_perm[row0 + arow] : -1;
    // B loads: 8 rows x 128 cols = 256 float4
    int brow = tid >> 5;
    int bcol = (tid & 31) * 4;

    for (int k0 = 0; k0 < D_IN; k0 += BK) {
        float4 av = (srcRow >= 0)
            ? *(const float4*)(x + (size_t)srcRow * D_IN + k0 + acol)
            : make_float4(0.f, 0.f, 0.f, 0.f);
        As[acol + 0][arow] = av.x;
        As[acol + 1][arow] = av.y;
        As[acol + 2][arow] = av.z;
        As[acol + 3][arow] = av.w;
        float4 bv = *(const float4*)(B + (size_t)(k0 + brow) * D_HID + colBase + bcol);
        *(float4*)&Bs[brow][bcol] = bv;
        __syncthreads();
        #pragma unroll
        for (int k = 0; k < BK; k++) {
            float a[TM], b[TN];
            #pragma unroll
            for (int i = 0; i < TM; i++) a[i] = As[k][tr + i];
            #pragma unroll
            for (int j = 0; j < TN; j++) b[j] = Bs[k][tc + j];
            #pragma unroll
            for (int i = 0; i < TM; i++)
                #pragma unroll
                for (int j = 0; j < TN; j++)
                    acc[i][j] = fmaf(a[i], b[j], acc[i][j]);
        }
        __syncthreads();
    }

    const float* b1d = b1 + dom * D_HID;
    #pragma unroll
    for (int i = 0; i < TM; i++) {
        int r = tr + i;
        if (r >= cnt) continue;
        float* hrow = g_h + (size_t)(row0 + r) * D_HID + colBase;
        #pragma unroll
        for (int j = 0; j < TN; j++)
            hrow[tc + j] = acc[i][j] + b1d[colBase + tc + j];
    }
}

// ---------------- LayerNorm + ReLU in-place on g_h ----------------
__global__ __launch_bounds__(256)
void ln_relu_kernel(const int* __restrict__ dom_types,
                    const float* __restrict__ gamma,
                    const float* __restrict__ beta) {
    int g = blockIdx.x;
    int dom = dom_types[g_perm[g]];
    float* h = g_h + (size_t)g * D_HID;
    int tid = threadIdx.x;

    float4 v = ((const float4*)h)[tid];
    float s  = v.x + v.y + v.z + v.w;
    float ss = v.x * v.x + v.y * v.y + v.z * v.z + v.w * v.w;

    // block reduction (256 threads = 8 warps)
    __shared__ float red_s[8], red_ss[8];
    #pragma unroll
    for (int o = 16; o > 0; o >>= 1) {
        s  += __shfl_down_sync(0xffffffffu, s, o);
        ss += __shfl_down_sync(0xffffffffu, ss, o);
    }
    if ((tid & 31) == 0) { red_s[tid >> 5] = s; red_ss[tid >> 5] = ss; }
    __syncthreads();
    if (tid < 8) { s = red_s[tid]; ss = red_ss[tid]; }
    if (tid < 8) {
        #pragma unroll
        for (int o = 4; o > 0; o >>= 1) {
            s  += __shfl_down_sync(0xffu, s, o);
            ss += __shfl_down_sync(0xffu, ss, o);
        }
        if (tid == 0) { red_s[0] = s; red_ss[0] = ss; }
    }
    __syncthreads();
    float mean = red_s[0] * (1.f / D_HID);
    float var  = red_ss[0] * (1.f / D_HID) - mean * mean;
    float rstd = rsqrtf(var + LN_EPS);

    const float* gm = gamma + dom * D_HID;
    const float* bt = beta  + dom * D_HID;
    int c = tid * 4;
    float4 gmv = *(const float4*)(gm + c);
    float4 btv = *(const float4*)(bt + c);
    float4 o;
    o.x = fmaxf((v.x - mean) * rstd * gmv.x + btv.x, 0.f);
    o.y = fmaxf((v.y - mean) * rstd * gmv.y + btv.y, 0.f);
    o.z = fmaxf((v.z - mean) * rstd * gmv.z + btv.z, 0.f);
    o.w = fmaxf((v.w - mean) * rstd * gmv.w + btv.w, 0.f);
    ((float4*)h)[tid] = o;
}

// ---------------- GEMM2: out[perm] = h @ W2[d] + b2[d] ----------------
__global__ __launch_bounds__(NTHREADS)
void gemm2_kernel(const float* __restrict__ W2,
                  const float* __restrict__ b2,
                  float* __restrict__ out) {
    int bt = blockIdx.x;
    if (bt >= g_ntiles) return;
    int dom  = g_tile_dom[bt];
    int row0 = g_tile_row[bt];
    int cnt  = g_tile_cnt[bt];
    int colBase = blockIdx.y * BN;

    const float* B = W2 + (size_t)dom * D_HID * D_OUT;

    __shared__ float As[BK][BM];
    __shared__ float Bs[BK][BN];

    int tid = threadIdx.x;
    int tr = (tid / 16) * TM;
    int tc = (tid % 16) * TN;

    float acc[TM][TN];
    #pragma unroll
    for (int i = 0; i < TM; i++)
        #pragma unroll
        for (int j = 0; j < TN; j++) acc[i][j] = 0.f;

    int arow = tid >> 1;
    int acol = (tid & 1) * 4;
    const float* Arow = (arow < cnt) ? (g_h + (size_t)(row0 + arow) * D_HID) : nullptr;
    int brow = tid >> 5;
    int bcol = (tid & 31) * 4;

    for (int k0 = 0; k0 < D_HID; k0 += BK) {
        float4 av = Arow ? *(const float4*)(Arow + k0 + acol)
                         : make_float4(0.f, 0.f, 0.f, 0.f);
        As[acol + 0][arow] = av.x;
        As[acol + 1][arow] = av.y;
        As[acol + 2][arow] = av.z;
        As[acol + 3][arow] = av.w;
        float4 bv = *(const float4*)(B + (size_t)(k0 + brow) * D_OUT + colBase + bcol);
        *(float4*)&Bs[brow][bcol] = bv;
        __syncthreads();
        #pragma unroll
        for (int k = 0; k < BK; k++) {
            float a[TM], b[TN];
            #pragma unroll
            for (int i = 0; i < TM; i++) a[i] = As[k][tr + i];
            #pragma unroll
            for (int j = 0; j < TN; j++) b[j] = Bs[k][tc + j];
            #pragma unroll
            for (int i = 0; i < TM; i++)
                #pragma unroll
                for (int j = 0; j < TN; j++)
                    acc[i][j] = fmaf(a[i], b[j], acc[i][j]);
        }
        __syncthreads();
    }

    const float* b2d = b2 + dom * D_OUT;
    #pragma unroll
    for (int i = 0; i < TM; i++) {
        int r = tr + i;
        if (r >= cnt) continue;
        int orig = g_perm[row0 + r];
        float* orow = out + (size_t)orig * D_OUT + colBase;
        #pragma unroll
        for (int j = 0; j < TN; j++)
            orow[tc + j] = acc[i][j] + b2d[colBase + tc + j];
    }
}

// ---------------- launch ----------------
extern "C" void kernel_launch(void* const* d_in, const int* in_sizes, int n_in,
                              void* d_out, int out_size) {
    const float* x     = (const float*)d_in[0];
    const int*   dom   = (const int*)  d_in[1];
    const float* W1    = (const float*)d_in[2];
    const float* b1    = (const float*)d_in[3];
    const float* gamma = (const float*)d_in[4];
    const float* beta  = (const float*)d_in[5];
    const float* W2    = (const float*)d_in[6];
    const float* b2    = (const float*)d_in[7];
    float* out = (float*)d_out;

    init_kernel<<<1, 32>>>();
    hist_kernel<<<(N_ROWS + 255) / 256, 256>>>(dom);
    plan_kernel<<<1, 32>>>();
    scatter_kernel<<<(N_ROWS + 255) / 256, 256>>>(dom);

    dim3 g1(MAX_TILES, D_HID / BN);
    gemm1_kernel<<<g1, NTHREADS>>>(x, W1, b1);

    ln_relu_kernel<<<N_ROWS, 256>>>(dom, gamma, beta);

    dim3 g2(MAX_TILES, D_OUT / BN);
    gemm2_kernel<<<g2, NTHREADS>>>(W2, b2, out);
}

// round 3
// speedup vs baseline: 1.8854x; 1.8854x over previous
#include <cuda_runtime.h>
#include <cuda_bf16.h>
#include <cstdint>

// ---------------- problem constants ----------------
#define N_ROWS   32768
#define D_IN     256
#define D_HID    1024
#define D_OUT    256
#define N_DOM    8
#define LN_EPS   1e-5f

#define BM 128
#define BN 128
#define BK 16
#define NTHREADS 256
#define MAX_TILES 384
#define RS_ 132            // smem row stride in floats

// ---------------- device scratch ----------------
__device__ int g_count[N_DOM], g_offset[N_DOM], g_fill[N_DOM];
__device__ int g_perm[N_ROWS];
__device__ int g_tile_dom[MAX_TILES], g_tile_row[MAX_TILES], g_tile_cnt[MAX_TILES];
__device__ int g_ntiles;
__device__ __align__(16) float  g_h[(size_t)N_ROWS * D_HID];     // 128 MiB
__device__ __align__(16) float2 g_part[(size_t)N_ROWS * 8];      // per-row (sum,sumsq) per 128-col tile

// ---------------- helpers ----------------
__device__ __forceinline__ uint32_t f2tf32(float f) {
    uint32_t u;
    asm("cvt.rna.tf32.f32 %0, %1;" : "=r"(u) : "f"(f));
    return u;
}

__device__ __forceinline__ void mma8(float* c, const uint32_t* a, const uint32_t* b) {
    asm volatile("mma.sync.aligned.m16n8k8.row.col.f32.tf32.tf32.f32 "
        "{%0,%1,%2,%3}, {%4,%5,%6,%7}, {%8,%9}, {%0,%1,%2,%3};"
        : "+f"(c[0]), "+f"(c[1]), "+f"(c[2]), "+f"(c[3])
        : "r"(a[0]), "r"(a[1]), "r"(a[2]), "r"(a[3]), "r"(b[0]), "r"(b[1]));
}

// ---------------- sort/plan kernels ----------------
__global__ void init_kernel() {
    int t = threadIdx.x;
    if (t < N_DOM) { g_count[t] = 0; g_fill[t] = 0; }
}
__global__ void hist_kernel(const int* __restrict__ dom) {
    int i = blockIdx.x * blockDim.x + threadIdx.x;
    if (i < N_ROWS) atomicAdd(&g_count[dom[i]], 1);
}
__global__ void plan_kernel() {
    if (threadIdx.x == 0 && blockIdx.x == 0) {
        int off = 0, nt = 0;
        for (int d = 0; d < N_DOM; d++) {
            g_offset[d] = off;
            int c = g_count[d];
            for (int t = 0; t < c; t += BM) {
                g_tile_dom[nt] = d;
                g_tile_row[nt] = off + t;
                g_tile_cnt[nt] = min(BM, c - t);
                nt++;
            }
            off += c;
        }
        g_ntiles = nt;
    }
}
__global__ void scatter_kernel(const int* __restrict__ dom) {
    int i = blockIdx.x * blockDim.x + threadIdx.x;
    if (i < N_ROWS) {
        int d = dom[i];
        int pos = g_offset[d] + atomicAdd(&g_fill[d], 1);
        g_perm[pos] = i;
    }
}

// ============================================================================
// GEMM1: h = gather(x) @ W1[d] + b1[d]; per-row (sum,sumsq) partials to g_part
// grid (MAX_TILES, 8)  — 128-row tile x 128-col tile, K=256
// ============================================================================
__global__ __launch_bounds__(NTHREADS, 1)
void gemm1_mma(const float* __restrict__ x,
               const float* __restrict__ W1,
               const float* __restrict__ b1) {
    __shared__ float As[2][BK * RS_];
    __shared__ float Bs[2][BK * RS_];
    __shared__ int sPerm[BM];

    int bt = blockIdx.x;
    if (bt >= g_ntiles) return;
    int dom  = g_tile_dom[bt];
    int row0 = g_tile_row[bt];
    int cnt  = g_tile_cnt[bt];
    int by   = blockIdx.y;
    int colBase = by * BN;

    int tid  = threadIdx.x;
    int lane = tid & 31, wid = tid >> 5;
    int wm = wid >> 1, wn = wid & 1;
    int lk = lane & 3, lm = lane >> 2;

    if (tid < BM) sPerm[tid] = (tid < cnt) ? g_perm[row0 + tid] : -1;
    __syncthreads();

    const float* W1d = W1 + (size_t)dom * D_IN * D_HID;

    float acc[2][8][4];
    #pragma unroll
    for (int i = 0; i < 2; i++)
        #pragma unroll
        for (int j = 0; j < 8; j++)
            #pragma unroll
            for (int q = 0; q < 4; q++) acc[i][j][q] = 0.f;

    // loader indices
    int arow0 = tid >> 2, af4 = tid & 3;      // A: 128 rows x 4 float4
    int arow1 = arow0 + 64;
    int bk0 = tid >> 5, bc4 = tid & 31;       // B: 16 k x 32 float4
    int bk1 = bk0 + 8;
    int ap0 = sPerm[arow0], ap1 = sPerm[arow1];

    float4 pa0, pa1, pb0, pb1;

    #define LDG1(k0) do {                                                           \
        pa0 = (ap0 >= 0) ? *(const float4*)(x + (size_t)ap0 * D_IN + (k0) + af4*4)  \
                         : make_float4(0.f,0.f,0.f,0.f);                            \
        pa1 = (ap1 >= 0) ? *(const float4*)(x + (size_t)ap1 * D_IN + (k0) + af4*4)  \
                         : make_float4(0.f,0.f,0.f,0.f);                            \
        pb0 = *(const float4*)(W1d + (size_t)((k0) + bk0) * D_HID + colBase + bc4*4);\
        pb1 = *(const float4*)(W1d + (size_t)((k0) + bk1) * D_HID + colBase + bc4*4);\
    } while (0)

    #define STS_AB(buf) do {                                                        \
        As[buf][(af4*4+0)*RS_ + arow0] = __uint_as_float(f2tf32(pa0.x));             \
        As[buf][(af4*4+1)*RS_ + arow0] = __uint_as_float(f2tf32(pa0.y));             \
        As[buf][(af4*4+2)*RS_ + arow0] = __uint_as_float(f2tf32(pa0.z));             \
        As[buf][(af4*4+3)*RS_ + arow0] = __uint_as_float(f2tf32(pa0.w));             \
        As[buf][(af4*4+0)*RS_ + arow1] = __uint_as_float(f2tf32(pa1.x));             \
        As[buf][(af4*4+1)*RS_ + arow1] = __uint_as_float(f2tf32(pa1.y));             \
        As[buf][(af4*4+2)*RS_ + arow1] = __uint_as_float(f2tf32(pa1.z));             \
        As[buf][(af4*4+3)*RS_ + arow1] = __uint_as_float(f2tf32(pa1.w));             \
        float4 cb0, cb1;                                                             \
        cb0.x = __uint_as_float(f2tf32(pb0.x)); cb0.y = __uint_as_float(f2tf32(pb0.y)); \
        cb0.z = __uint_as_float(f2tf32(pb0.z)); cb0.w = __uint_as_float(f2tf32(pb0.w)); \
        cb1.x = __uint_as_float(f2tf32(pb1.x)); cb1.y = __uint_as_float(f2tf32(pb1.y)); \
        cb1.z = __uint_as_float(f2tf32(pb1.z)); cb1.w = __uint_as_float(f2tf32(pb1.w)); \
        *(float4*)&Bs[buf][bk0*RS_ + bc4*4] = cb0;                                   \
        *(float4*)&Bs[buf][bk1*RS_ + bc4*4] = cb1;                                   \
    } while (0)

    #define COMPUTE(buf) do {                                                       \
        _Pragma("unroll")                                                            \
        for (int kk = 0; kk < BK; kk += 8) {                                         \
            uint32_t a[2][4], b[8][2];                                               \
            const float* A_ = &As[buf][(kk + lk)*RS_ + wm*32 + lm];                  \
            _Pragma("unroll")                                                        \
            for (int mf = 0; mf < 2; mf++) {                                         \
                a[mf][0] = __float_as_uint(A_[mf*16]);                               \
                a[mf][1] = __float_as_uint(A_[mf*16 + 8]);                           \
                a[mf][2] = __float_as_uint(A_[4*RS_ + mf*16]);                       \
                a[mf][3] = __float_as_uint(A_[4*RS_ + mf*16 + 8]);                   \
            }                                                                        \
            const float* B_ = &Bs[buf][(kk + lk)*RS_ + wn*64 + lm];                  \
            _Pragma("unroll")                                                        \
            for (int nf = 0; nf < 8; nf++) {                                         \
                b[nf][0] = __float_as_uint(B_[nf*8]);                                \
                b[nf][1] = __float_as_uint(B_[4*RS_ + nf*8]);                        \
            }                                                                        \
            _Pragma("unroll")                                                        \
            for (int mf = 0; mf < 2; mf++)                                           \
                _Pragma("unroll")                                                    \
                for (int nf = 0; nf < 8; nf++)                                       \
                    mma8(acc[mf][nf], a[mf], b[nf]);                                 \
        }                                                                            \
    } while (0)

    LDG1(0);
    STS_AB(0);
    __syncthreads();

    const int NC = D_IN / BK;  // 16
    for (int c = 0; c < NC; c++) {
        int buf = c & 1;
        if (c + 1 < NC) LDG1((c + 1) * BK);
        COMPUTE(buf);
        if (c + 1 < NC) {
            STS_AB((c + 1) & 1);
            __syncthreads();
        }
    }

    // ---- epilogue: bias add, store h, per-row stats ----
    float2* sStat = (float2*)&As[0][0];   // 128 rows x 2 warp_n
    const float* b1d = b1 + (size_t)dom * D_HID + colBase + wn * 64;

    #pragma unroll
    for (int mf = 0; mf < 2; mf++) {
        #pragma unroll
        for (int rsel = 0; rsel < 2; rsel++) {
            int r = wm * 32 + mf * 16 + lm + rsel * 8;
            float s = 0.f, ss = 0.f;
            float* hrow = g_h + (size_t)(row0 + r) * D_HID + colBase + wn * 64;
            bool wr = (r < cnt);
            #pragma unroll
            for (int nf = 0; nf < 8; nf++) {
                int cc = nf * 8 + 2 * lk;
                float v0 = acc[mf][nf][rsel * 2 + 0] + __ldg(b1d + cc);
                float v1 = acc[mf][nf][rsel * 2 + 1] + __ldg(b1d + cc + 1);
                s += v0 + v1;
                ss += v0 * v0 + v1 * v1;
                if (wr) *(float2*)(hrow + cc) = make_float2(v0, v1);
            }
            s  += __shfl_xor_sync(0xffffffffu, s, 1);
            s  += __shfl_xor_sync(0xffffffffu, s, 2);
            ss += __shfl_xor_sync(0xffffffffu, ss, 1);
            ss += __shfl_xor_sync(0xffffffffu, ss, 2);
            if (lk == 0) sStat[r * 2 + wn] = make_float2(s, ss);
        }
    }
    __syncthreads();
    if (tid < BM && tid < cnt) {
        float2 p0 = sStat[tid * 2 + 0];
        float2 p1 = sStat[tid * 2 + 1];
        g_part[(size_t)(row0 + tid) * 8 + by] = make_float2(p0.x + p1.x, p0.y + p1.y);
    }
    #undef LDG1
    #undef STS_AB
    #undef COMPUTE
}

// ============================================================================
// GEMM2: out[perm] = relu(LN(h)*gamma+beta) @ W2[d] + b2[d]
// grid (MAX_TILES, 2) — K=1024
// ============================================================================
__global__ __launch_bounds__(NTHREADS, 1)
void gemm2_mma(const float* __restrict__ W2,
               const float* __restrict__ gamma,
               const float* __restrict__ beta,
               const float* __restrict__ b2,
               float* __restrict__ out) {
    __shared__ float As[2][BK * RS_];
    __shared__ float Bs[2][BK * RS_];
    __shared__ float sG[D_HID], sBt[D_HID];
    __shared__ float sMu[BM], sRs[BM];
    __shared__ int sPerm[BM];

    int bt = blockIdx.x;
    if (bt >= g_ntiles) return;
    int dom  = g_tile_dom[bt];
    int row0 = g_tile_row[bt];
    int cnt  = g_tile_cnt[bt];
    int colBase = blockIdx.y * BN;

    int tid  = threadIdx.x;
    int lane = tid & 31, wid = tid >> 5;
    int wm = wid >> 1, wn = wid & 1;
    int lk = lane & 3, lm = lane >> 2;

    for (int i = tid; i < D_HID; i += NTHREADS) {
        sG[i]  = gamma[(size_t)dom * D_HID + i];
        sBt[i] = beta[(size_t)dom * D_HID + i];
    }
    if (tid < BM) {
        sPerm[tid] = (tid < cnt) ? g_perm[row0 + tid] : -1;
        float mu = 0.f, rs = 0.f;
        if (tid < cnt) {
            float s = 0.f, ss = 0.f;
            #pragma unroll
            for (int q = 0; q < 8; q++) {
                float2 p = g_part[(size_t)(row0 + tid) * 8 + q];
                s += p.x; ss += p.y;
            }
            mu = s * (1.f / D_HID);
            float var = ss * (1.f / D_HID) - mu * mu;
            rs = rsqrtf(var + LN_EPS);
        }
        sMu[tid] = mu; sRs[tid] = rs;
    }
    __syncthreads();

    const float* W2d = W2 + (size_t)dom * D_HID * D_OUT;

    float acc[2][8][4];
    #pragma unroll
    for (int i = 0; i < 2; i++)
        #pragma unroll
        for (int j = 0; j < 8; j++)
            #pragma unroll
            for (int q = 0; q < 4; q++) acc[i][j][q] = 0.f;

    int arow0 = tid >> 2, af4 = tid & 3;
    int arow1 = arow0 + 64;
    int bk0 = tid >> 5, bc4 = tid & 31;
    int bk1 = bk0 + 8;
    bool av0 = (arow0 < cnt), av1 = (arow1 < cnt);
    float mu0 = sMu[arow0], rs0 = sRs[arow0];
    float mu1 = sMu[arow1], rs1 = sRs[arow1];

    float4 pa0, pa1, pb0, pb1;

    #define LDG2(k0) do {                                                            \
        pa0 = av0 ? *(const float4*)(g_h + (size_t)(row0 + arow0) * D_HID + (k0) + af4*4) \
                  : make_float4(0.f,0.f,0.f,0.f);                                     \
        pa1 = av1 ? *(const float4*)(g_h + (size_t)(row0 + arow1) * D_HID + (k0) + af4*4) \
                  : make_float4(0.f,0.f,0.f,0.f);                                     \
        pb0 = *(const float4*)(W2d + (size_t)((k0) + bk0) * D_OUT + colBase + bc4*4); \
        pb1 = *(const float4*)(W2d + (size_t)((k0) + bk1) * D_OUT + colBase + bc4*4); \
    } while (0)

    #define LN4(v, mu, rs, kb) do {                                                  \
        (v).x = fmaxf(fmaf(((v).x - (mu)) * (rs), sG[(kb)+0], sBt[(kb)+0]), 0.f);     \
        (v).y = fmaxf(fmaf(((v).y - (mu)) * (rs), sG[(kb)+1], sBt[(kb)+1]), 0.f);     \
        (v).z = fmaxf(fmaf(((v).z - (mu)) * (rs), sG[(kb)+2], sBt[(kb)+2]), 0.f);     \
        (v).w = fmaxf(fmaf(((v).w - (mu)) * (rs), sG[(kb)+3], sBt[(kb)+3]), 0.f);     \
    } while (0)

    #define STS_AB2(buf, k0) do {                                                    \
        float4 qa0 = pa0, qa1 = pa1;                                                 \
        if (av0) LN4(qa0, mu0, rs0, (k0) + af4*4);                                    \
        if (av1) LN4(qa1, mu1, rs1, (k0) + af4*4);                                    \
        As[buf][(af4*4+0)*RS_ + arow0] = __uint_as_float(f2tf32(qa0.x));              \
        As[buf][(af4*4+1)*RS_ + arow0] = __uint_as_float(f2tf32(qa0.y));              \
        As[buf][(af4*4+2)*RS_ + arow0] = __uint_as_float(f2tf32(qa0.z));              \
        As[buf][(af4*4+3)*RS_ + arow0] = __uint_as_float(f2tf32(qa0.w));              \
        As[buf][(af4*4+0)*RS_ + arow1] = __uint_as_float(f2tf32(qa1.x));              \
        As[buf][(af4*4+1)*RS_ + arow1] = __uint_as_float(f2tf32(qa1.y));              \
        As[buf][(af4*4+2)*RS_ + arow1] = __uint_as_float(f2tf32(qa1.z));              \
        As[buf][(af4*4+3)*RS_ + arow1] = __uint_as_float(f2tf32(qa1.w));              \
        float4 cb0, cb1;                                                              \
        cb0.x = __uint_as_float(f2tf32(pb0.x)); cb0.y = __uint_as_float(f2tf32(pb0.y)); \
        cb0.z = __uint_as_float(f2tf32(pb0.z)); cb0.w = __uint_as_float(f2tf32(pb0.w)); \
        cb1.x = __uint_as_float(f2tf32(pb1.x)); cb1.y = __uint_as_float(f2tf32(pb1.y)); \
        cb1.z = __uint_as_float(f2tf32(pb1.z)); cb1.w = __uint_as_float(f2tf32(pb1.w)); \
        *(float4*)&Bs[buf][bk0*RS_ + bc4*4] = cb0;                                    \
        *(float4*)&Bs[buf][bk1*RS_ + bc4*4] = cb1;                                    \
    } while (0)

    #define COMPUTE2(buf) do {                                                       \
        _Pragma("unroll")                                                             \
        for (int kk = 0; kk < BK; kk += 8) {                                          \
            uint32_t a[2][4], b[8][2];                                                \
            const float* A_ = &As[buf][(kk + lk)*RS_ + wm*32 + lm];                   \
            _Pragma("unroll")                                                         \
            for (int mf = 0; mf < 2; mf++) {                                          \
                a[mf][0] = __float_as_uint(A_[mf*16]);                                \
                a[mf][1] = __float_as_uint(A_[mf*16 + 8]);                            \
                a[mf][2] = __float_as_uint(A_[4*RS_ + mf*16]);                        \
                a[mf][3] = __float_as_uint(A_[4*RS_ + mf*16 + 8]);                    \
            }                                                                         \
            const float* B_ = &Bs[buf][(kk + lk)*RS_ + wn*64 + lm];                   \
            _Pragma("unroll")                                                         \
            for (int nf = 0; nf < 8; nf++) {                                          \
                b[nf][0] = __float_as_uint(B_[nf*8]);                                 \
                b[nf][1] = __float_as_uint(B_[4*RS_ + nf*8]);                         \
            }                                                                         \
            _Pragma("unroll")                                                         \
            for (int mf = 0; mf < 2; mf++)                                            \
                _Pragma("unroll")                                                     \
                for (int nf = 0; nf < 8; nf++)                                        \
                    mma8(acc[mf][nf], a[mf], b[nf]);                                  \
        }                                                                             \
    } while (0)

    LDG2(0);
    STS_AB2(0, 0);
    __syncthreads();

    const int NC = D_HID / BK;  // 64
    for (int c = 0; c < NC; c++) {
        int buf = c & 1;
        if (c + 1 < NC) LDG2((c + 1) * BK);
        COMPUTE2(buf);
        if (c + 1 < NC) {
            STS_AB2((c + 1) & 1, (c + 1) * BK);
            __syncthreads();
        }
    }

    // ---- epilogue: bias add, scatter to out ----
    const float* b2d = b2 + (size_t)dom * D_OUT + colBase + wn * 64;
    #pragma unroll
    for (int mf = 0; mf < 2; mf++) {
        #pragma unroll
        for (int rsel = 0; rsel < 2; rsel++) {
            int r = wm * 32 + mf * 16 + lm + rsel * 8;
            int src = sPerm[r];
            if (src < 0) continue;
            float* orow = out + (size_t)src * D_OUT + colBase + wn * 64;
            #pragma unroll
            for (int nf = 0; nf < 8; nf++) {
                int cc = nf * 8 + 2 * lk;
                float v0 = acc[mf][nf][rsel * 2 + 0] + __ldg(b2d + cc);
                float v1 = acc[mf][nf][rsel * 2 + 1] + __ldg(b2d + cc + 1);
                *(float2*)(orow + cc) = make_float2(v0, v1);
            }
        }
    }
    #undef LDG2
    #undef LN4
    #undef STS_AB2
    #undef COMPUTE2
}

// ---------------- launch ----------------
extern "C" void kernel_launch(void* const* d_in, const int* in_sizes, int n_in,
                              void* d_out, int out_size) {
    const float* x     = (const float*)d_in[0];
    const int*   dom   = (const int*)  d_in[1];
    const float* W1    = (const float*)d_in[2];
    const float* b1    = (const float*)d_in[3];
    const float* gamma = (const float*)d_in[4];
    const float* beta  = (const float*)d_in[5];
    const float* W2    = (const float*)d_in[6];
    const float* b2    = (const float*)d_in[7];
    float* out = (float*)d_out;

    init_kernel<<<1, 32>>>();
    hist_kernel<<<(N_ROWS + 255) / 256, 256>>>(dom);
    plan_kernel<<<1, 32>>>();
    scatter_kernel<<<(N_ROWS + 255) / 256, 256>>>(dom);

    dim3 grid1(MAX_TILES, D_HID / BN);   // (384, 8)
    gemm1_mma<<<grid1, NTHREADS>>>(x, W1, b1);

    dim3 grid2(MAX_TILES, D_OUT / BN);   // (384, 2)
    gemm2_mma<<<grid2, NTHREADS>>>(W2, gamma, beta, b2, out);
}

// round 4
// speedup vs baseline: 2.7972x; 1.4836x over previous
#include <cuda_runtime.h>
#include <cuda_bf16.h>
#include <cstdint>

// ---------------- problem constants ----------------
#define N_ROWS   32768
#define D_IN     256
#define D_HID    1024
#define D_OUT    256
#define N_DOM    8
#define LN_EPS   1e-5f

#define BM 128
#define BN 256
#define BK 16
#define NTHREADS 256
#define MAX_TILES 384
#define RSA 132            // A smem row stride (floats)
#define RSB 264            // B smem row stride (floats), 264 % 32 == 8 -> conflict-free frags

// ---------------- device scratch ----------------
__device__ int g_count[N_DOM], g_offset[N_DOM], g_fill[N_DOM];
__device__ int g_perm[N_ROWS];
__device__ int g_tile_dom[MAX_TILES], g_tile_row[MAX_TILES], g_tile_cnt[MAX_TILES];
__device__ int g_ntiles;
__device__ __align__(16) float  g_h[(size_t)N_ROWS * D_HID];     // 128 MiB
__device__ __align__(16) float2 g_part[(size_t)N_ROWS * 4];      // per-row (sum,sumsq) per 256-col tile

// ---------------- smem layout (dynamic) ----------------
#define OFF_AS   0
#define SZ_AS    (2 * BK * RSA * 4)            // 16896
#define OFF_BS   (OFF_AS + SZ_AS)
#define SZ_BS    (2 * BK * RSB * 4)            // 33792
#define OFF_END  (OFF_BS + SZ_BS)              // 50688
// GEMM1 extras
#define G1_PERM  OFF_END
#define G1_STAT  (OFF_END + 512)               // 128 rows x 4 wn x float2 = 4096
#define SMEM1_TOTAL (OFF_END + 512 + 4096)
// GEMM2 extras
#define G2_G     OFF_END
#define G2_B     (OFF_END + 4096)
#define G2_MU    (OFF_END + 8192)
#define G2_RS    (OFF_END + 8704)
#define G2_PERM  (OFF_END + 9216)
#define SMEM2_TOTAL (OFF_END + 9728)

// ---------------- helpers ----------------
__device__ __forceinline__ uint32_t f2tf32(float f) {
    uint32_t u;
    asm("cvt.rna.tf32.f32 %0, %1;" : "=r"(u) : "f"(f));
    return u;
}
__device__ __forceinline__ void mma8(float* c, const uint32_t* a, const uint32_t* b) {
    asm volatile("mma.sync.aligned.m16n8k8.row.col.f32.tf32.tf32.f32 "
        "{%0,%1,%2,%3}, {%4,%5,%6,%7}, {%8,%9}, {%0,%1,%2,%3};"
        : "+f"(c[0]), "+f"(c[1]), "+f"(c[2]), "+f"(c[3])
        : "r"(a[0]), "r"(a[1]), "r"(a[2]), "r"(a[3]), "r"(b[0]), "r"(b[1]));
}

// ---------------- sort/plan kernels ----------------
__global__ void init_kernel() {
    int t = threadIdx.x;
    if (t < N_DOM) { g_count[t] = 0; g_fill[t] = 0; }
}
__global__ void hist_kernel(const int* __restrict__ dom) {
    int i = blockIdx.x * blockDim.x + threadIdx.x;
    if (i < N_ROWS) atomicAdd(&g_count[dom[i]], 1);
}
__global__ void plan_kernel() {
    if (threadIdx.x == 0 && blockIdx.x == 0) {
        int off = 0, nt = 0;
        for (int d = 0; d < N_DOM; d++) {
            g_offset[d] = off;
            int c = g_count[d];
            for (int t = 0; t < c; t += BM) {
                g_tile_dom[nt] = d;
                g_tile_row[nt] = off + t;
                g_tile_cnt[nt] = min(BM, c - t);
                nt++;
            }
            off += c;
        }
        g_ntiles = nt;
    }
}
__global__ void scatter_kernel(const int* __restrict__ dom) {
    int i = blockIdx.x * blockDim.x + threadIdx.x;
    if (i < N_ROWS) {
        int d = dom[i];
        int pos = g_offset[d] + atomicAdd(&g_fill[d], 1);
        g_perm[pos] = i;
    }
}

// ---------------- shared fragment compute ----------------
#define COMPUTE_FRAGS(As_, Bs_) do {                                                 \
    _Pragma("unroll")                                                                 \
    for (int kk = 0; kk < BK; kk += 8) {                                              \
        uint32_t a[4][4], b[8][2];                                                    \
        const float* A_ = &(As_)[(kk + lk) * RSA + wm * 64 + lm];                     \
        _Pragma("unroll")                                                             \
        for (int mf = 0; mf < 4; mf++) {                                              \
            a[mf][0] = __float_as_uint(A_[mf * 16]);                                  \
            a[mf][1] = __float_as_uint(A_[mf * 16 + 8]);                              \
            a[mf][2] = __float_as_uint(A_[4 * RSA + mf * 16]);                        \
            a[mf][3] = __float_as_uint(A_[4 * RSA + mf * 16 + 8]);                    \
        }                                                                             \
        const float* B_ = &(Bs_)[(kk + lk) * RSB + wn * 64 + lm];                     \
        _Pragma("unroll")                                                             \
        for (int nf = 0; nf < 8; nf++) {                                              \
            b[nf][0] = __float_as_uint(B_[nf * 8]);                                   \
            b[nf][1] = __float_as_uint(B_[4 * RSB + nf * 8]);                         \
        }                                                                             \
        _Pragma("unroll")                                                             \
        for (int mf = 0; mf < 4; mf++)                                                \
            _Pragma("unroll")                                                         \
            for (int nf = 0; nf < 8; nf++)                                            \
                mma8(acc[mf][nf], a[mf], b[nf]);                                      \
    }                                                                                 \
} while (0)

#define STS_A(As_) do {                                                               \
    (As_)[(af4 * 4 + 0) * RSA + arow0] = __uint_as_float(f2tf32(pa0.x));              \
    (As_)[(af4 * 4 + 1) * RSA + arow0] = __uint_as_float(f2tf32(pa0.y));              \
    (As_)[(af4 * 4 + 2) * RSA + arow0] = __uint_as_float(f2tf32(pa0.z));              \
    (As_)[(af4 * 4 + 3) * RSA + arow0] = __uint_as_float(f2tf32(pa0.w));              \
    (As_)[(af4 * 4 + 0) * RSA + arow1] = __uint_as_float(f2tf32(pa1.x));              \
    (As_)[(af4 * 4 + 1) * RSA + arow1] = __uint_as_float(f2tf32(pa1.y));              \
    (As_)[(af4 * 4 + 2) * RSA + arow1] = __uint_as_float(f2tf32(pa1.z));              \
    (As_)[(af4 * 4 + 3) * RSA + arow1] = __uint_as_float(f2tf32(pa1.w));              \
} while (0)

#define STS_B(Bs_) do {                                                               \
    float4 c0, c1, c2, c3;                                                            \
    c0.x = __uint_as_float(f2tf32(pb0.x)); c0.y = __uint_as_float(f2tf32(pb0.y));     \
    c0.z = __uint_as_float(f2tf32(pb0.z)); c0.w = __uint_as_float(f2tf32(pb0.w));     \
    c1.x = __uint_as_float(f2tf32(pb1.x)); c1.y = __uint_as_float(f2tf32(pb1.y));     \
    c1.z = __uint_as_float(f2tf32(pb1.z)); c1.w = __uint_as_float(f2tf32(pb1.w));     \
    c2.x = __uint_as_float(f2tf32(pb2.x)); c2.y = __uint_as_float(f2tf32(pb2.y));     \
    c2.z = __uint_as_float(f2tf32(pb2.z)); c2.w = __uint_as_float(f2tf32(pb2.w));     \
    c3.x = __uint_as_float(f2tf32(pb3.x)); c3.y = __uint_as_float(f2tf32(pb3.y));     \
    c3.z = __uint_as_float(f2tf32(pb3.z)); c3.w = __uint_as_float(f2tf32(pb3.w));     \
    *(float4*)&(Bs_)[bk0 * RSB + bc * 4]        = c0;                                 \
    *(float4*)&(Bs_)[bk0 * RSB + 128 + bc * 4]  = c1;                                 \
    *(float4*)&(Bs_)[bk1 * RSB + bc * 4]        = c2;                                 \
    *(float4*)&(Bs_)[bk1 * RSB + 128 + bc * 4]  = c3;                                 \
} while (0)

// ============================================================================
// GEMM1: h = gather(x) @ W1[d] + b1[d]; per-row (sum,sumsq) partials
// grid (MAX_TILES, 4) — CTA 128x256, K=256
// ============================================================================
__global__ __launch_bounds__(NTHREADS, 1)
void gemm1_mma(const float* __restrict__ x,
               const float* __restrict__ W1,
               const float* __restrict__ b1) {
    extern __shared__ __align__(16) char smem[];
    float* As = (float*)(smem + OFF_AS);
    float* Bs = (float*)(smem + OFF_BS);
    int*   sPerm = (int*)(smem + G1_PERM);
    float2* sStat = (float2*)(smem + G1_STAT);

    int bt = blockIdx.x;
    if (bt >= g_ntiles) return;
    int dom  = g_tile_dom[bt];
    int row0 = g_tile_row[bt];
    int cnt  = g_tile_cnt[bt];
    int by   = blockIdx.y;
    int colBase = by * BN;

    int tid  = threadIdx.x;
    int lane = tid & 31, wid = tid >> 5;
    int wm = wid >> 2, wn = wid & 3;
    int lk = lane & 3, lm = lane >> 2;

    if (tid < BM) sPerm[tid] = (tid < cnt) ? g_perm[row0 + tid] : -1;
    __syncthreads();

    const float* W1d = W1 + (size_t)dom * D_IN * D_HID;

    float acc[4][8][4];
    #pragma unroll
    for (int i = 0; i < 4; i++)
        #pragma unroll
        for (int j = 0; j < 8; j++)
            #pragma unroll
            for (int q = 0; q < 4; q++) acc[i][j][q] = 0.f;

    int arow0 = tid >> 2, af4 = tid & 3;
    int arow1 = arow0 + 64;
    int bk0 = tid >> 5, bc = tid & 31;
    int bk1 = bk0 + 8;
    int ap0 = sPerm[arow0], ap1 = sPerm[arow1];

    float4 pa0, pa1, pb0, pb1, pb2, pb3;

    #define LDG1(k0) do {                                                             \
        pa0 = (ap0 >= 0) ? *(const float4*)(x + (size_t)ap0 * D_IN + (k0) + af4 * 4)  \
                         : make_float4(0.f, 0.f, 0.f, 0.f);                            \
        pa1 = (ap1 >= 0) ? *(const float4*)(x + (size_t)ap1 * D_IN + (k0) + af4 * 4)  \
                         : make_float4(0.f, 0.f, 0.f, 0.f);                            \
        const float* Bp0 = W1d + (size_t)((k0) + bk0) * D_HID + colBase + bc * 4;      \
        const float* Bp1 = W1d + (size_t)((k0) + bk1) * D_HID + colBase + bc * 4;      \
        pb0 = *(const float4*)(Bp0);                                                   \
        pb1 = *(const float4*)(Bp0 + 128);                                             \
        pb2 = *(const float4*)(Bp1);                                                   \
        pb3 = *(const float4*)(Bp1 + 128);                                             \
    } while (0)

    LDG1(0);
    STS_A(As); STS_B(Bs);
    __syncthreads();

    const int NC = D_IN / BK;  // 16
    for (int c = 0; c < NC; c++) {
        float* Ac = As + (c & 1) * BK * RSA;
        float* Bc = Bs + (c & 1) * BK * RSB;
        if (c + 1 < NC) LDG1((c + 1) * BK);
        COMPUTE_FRAGS(Ac, Bc);
        if (c + 1 < NC) {
            float* An = As + ((c + 1) & 1) * BK * RSA;
            float* Bn = Bs + ((c + 1) & 1) * BK * RSB;
            STS_A(An); STS_B(Bn);
            __syncthreads();
        }
    }
    #undef LDG1

    // ---- epilogue: bias add, store h, per-row stats ----
    __syncthreads();
    const float* b1d = b1 + (size_t)dom * D_HID + colBase + wn * 64;
    #pragma unroll
    for (int mf = 0; mf < 4; mf++) {
        #pragma unroll
        for (int rsel = 0; rsel < 2; rsel++) {
            int r = wm * 64 + mf * 16 + lm + rsel * 8;
            float s = 0.f, ss = 0.f;
            float* hrow = g_h + (size_t)(row0 + r) * D_HID + colBase + wn * 64;
            bool wr = (r < cnt);
            #pragma unroll
            for (int nf = 0; nf < 8; nf++) {
                int cc = nf * 8 + 2 * lk;
                float v0 = acc[mf][nf][rsel * 2 + 0] + __ldg(b1d + cc);
                float v1 = acc[mf][nf][rsel * 2 + 1] + __ldg(b1d + cc + 1);
                s += v0 + v1;
                ss += v0 * v0 + v1 * v1;
                if (wr) *(float2*)(hrow + cc) = make_float2(v0, v1);
            }
            s  += __shfl_xor_sync(0xffffffffu, s, 1);
            s  += __shfl_xor_sync(0xffffffffu, s, 2);
            ss += __shfl_xor_sync(0xffffffffu, ss, 1);
            ss += __shfl_xor_sync(0xffffffffu, ss, 2);
            if (lk == 0) sStat[r * 4 + wn] = make_float2(s, ss);
        }
    }
    __syncthreads();
    if (tid < BM && tid < cnt) {
        float s = 0.f, ss = 0.f;
        #pragma unroll
        for (int q = 0; q < 4; q++) {
            float2 p = sStat[tid * 4 + q];
            s += p.x; ss += p.y;
        }
        g_part[(size_t)(row0 + tid) * 4 + by] = make_float2(s, ss);
    }
}

// ============================================================================
// GEMM2: out[perm] = relu(LN(h)*gamma+beta) @ W2[d] + b2[d]
// grid (MAX_TILES) — CTA 128x256 (full D_OUT), K=1024
// ============================================================================
__global__ __launch_bounds__(NTHREADS, 1)
void gemm2_mma(const float* __restrict__ W2,
               const float* __restrict__ gamma,
               const float* __restrict__ beta,
               const float* __restrict__ b2,
               float* __restrict__ out) {
    extern __shared__ __align__(16) char smem[];
    float* As = (float*)(smem + OFF_AS);
    float* Bs = (float*)(smem + OFF_BS);
    float* sG  = (float*)(smem + G2_G);
    float* sBt = (float*)(smem + G2_B);
    float* sMu = (float*)(smem + G2_MU);
    float* sRs = (float*)(smem + G2_RS);
    int*   sPerm = (int*)(smem + G2_PERM);

    int bt = blockIdx.x;
    if (bt >= g_ntiles) return;
    int dom  = g_tile_dom[bt];
    int row0 = g_tile_row[bt];
    int cnt  = g_tile_cnt[bt];

    int tid  = threadIdx.x;
    int lane = tid & 31, wid = tid >> 5;
    int wm = wid >> 2, wn = wid & 3;
    int lk = lane & 3, lm = lane >> 2;

    for (int i = tid; i < D_HID; i += NTHREADS) {
        sG[i]  = gamma[(size_t)dom * D_HID + i];
        sBt[i] = beta[(size_t)dom * D_HID + i];
    }
    if (tid < BM) {
        sPerm[tid] = (tid < cnt) ? g_perm[row0 + tid] : -1;
        float mu = 0.f, rs = 0.f;
        if (tid < cnt) {
            float s = 0.f, ss = 0.f;
            #pragma unroll
            for (int q = 0; q < 4; q++) {
                float2 p = g_part[(size_t)(row0 + tid) * 4 + q];
                s += p.x; ss += p.y;
            }
            mu = s * (1.f / D_HID);
            float var = ss * (1.f / D_HID) - mu * mu;
            rs = rsqrtf(var + LN_EPS);
        }
        sMu[tid] = mu; sRs[tid] = rs;
    }
    __syncthreads();

    const float* W2d = W2 + (size_t)dom * D_HID * D_OUT;

    float acc[4][8][4];
    #pragma unroll
    for (int i = 0; i < 4; i++)
        #pragma unroll
        for (int j = 0; j < 8; j++)
            #pragma unroll
            for (int q = 0; q < 4; q++) acc[i][j][q] = 0.f;

    int arow0 = tid >> 2, af4 = tid & 3;
    int arow1 = arow0 + 64;
    int bk0 = tid >> 5, bc = tid & 31;
    int bk1 = bk0 + 8;
    bool av0 = (arow0 < cnt), av1 = (arow1 < cnt);
    float mu0 = sMu[arow0], rs0 = sRs[arow0];
    float mu1 = sMu[arow1], rs1 = sRs[arow1];

    float4 pa0, pa1, pb0, pb1, pb2, pb3;

    #define LN4(v, mu, rs, kb) do {                                                   \
        (v).x = fmaxf(fmaf(((v).x - (mu)) * (rs), sG[(kb) + 0], sBt[(kb) + 0]), 0.f);  \
        (v).y = fmaxf(fmaf(((v).y - (mu)) * (rs), sG[(kb) + 1], sBt[(kb) + 1]), 0.f);  \
        (v).z = fmaxf(fmaf(((v).z - (mu)) * (rs), sG[(kb) + 2], sBt[(kb) + 2]), 0.f);  \
        (v).w = fmaxf(fmaf(((v).w - (mu)) * (rs), sG[(kb) + 3], sBt[(kb) + 3]), 0.f);  \
    } while (0)

    #define LDG2(k0) do {                                                             \
        pa0 = av0 ? *(const float4*)(g_h + (size_t)(row0 + arow0) * D_HID + (k0) + af4 * 4) \
                  : make_float4(0.f, 0.f, 0.f, 0.f);                                   \
        pa1 = av1 ? *(const float4*)(g_h + (size_t)(row0 + arow1) * D_HID + (k0) + af4 * 4) \
                  : make_float4(0.f, 0.f, 0.f, 0.f);                                   \
        const float* Bp0 = W2d + (size_t)((k0) + bk0) * D_OUT + bc * 4;                \
        const float* Bp1 = W2d + (size_t)((k0) + bk1) * D_OUT + bc * 4;                \
        pb0 = *(const float4*)(Bp0);                                                   \
        pb1 = *(const float4*)(Bp0 + 128);                                             \
        pb2 = *(const float4*)(Bp1);                                                   \
        pb3 = *(const float4*)(Bp1 + 128);                                             \
    } while (0)

    #define PREP_A(k0) do {                                                           \
        if (av0) LN4(pa0, mu0, rs0, (k0) + af4 * 4);                                   \
        if (av1) LN4(pa1, mu1, rs1, (k0) + af4 * 4);                                   \
    } while (0)

    LDG2(0);
    PREP_A(0);
    STS_A(As); STS_B(Bs);
    __syncthreads();

    const int NC = D_HID / BK;  // 64
    for (int c = 0; c < NC; c++) {
        float* Ac = As + (c & 1) * BK * RSA;
        float* Bc = Bs + (c & 1) * BK * RSB;
        if (c + 1 < NC) LDG2((c + 1) * BK);
        COMPUTE_FRAGS(Ac, Bc);
        if (c + 1 < NC) {
            PREP_A((c + 1) * BK);
            float* An = As + ((c + 1) & 1) * BK * RSA;
            float* Bn = Bs + ((c + 1) & 1) * BK * RSB;
            STS_A(An); STS_B(Bn);
            __syncthreads();
        }
    }
    #undef LDG2
    #undef LN4
    #undef PREP_A

    // ---- epilogue: bias add, scatter to out ----
    const float* b2d = b2 + (size_t)dom * D_OUT + wn * 64;
    #pragma unroll
    for (int mf = 0; mf < 4; mf++) {
        #pragma unroll
        for (int rsel = 0; rsel < 2; rsel++) {
            int r = wm * 64 + mf * 16 + lm + rsel * 8;
            int src = sPerm[r];
            if (src < 0) continue;
            float* orow = out + (size_t)src * D_OUT + wn * 64;
            #pragma unroll
            for (int nf = 0; nf < 8; nf++) {
                int cc = nf * 8 + 2 * lk;
                float v0 = acc[mf][nf][rsel * 2 + 0] + __ldg(b2d + cc);
                float v1 = acc[mf][nf][rsel * 2 + 1] + __ldg(b2d + cc + 1);
                *(float2*)(orow + cc) = make_float2(v0, v1);
            }
        }
    }
}

// ---------------- launch ----------------
extern "C" void kernel_launch(void* const* d_in, const int* in_sizes, int n_in,
                              void* d_out, int out_size) {
    const float* x     = (const float*)d_in[0];
    const int*   dom   = (const int*)  d_in[1];
    const float* W1    = (const float*)d_in[2];
    const float* b1    = (const float*)d_in[3];
    const float* gamma = (const float*)d_in[4];
    const float* beta  = (const float*)d_in[5];
    const float* W2    = (const float*)d_in[6];
    const float* b2    = (const float*)d_in[7];
    float* out = (float*)d_out;

    cudaFuncSetAttribute(gemm1_mma, cudaFuncAttributeMaxDynamicSharedMemorySize, SMEM1_TOTAL);
    cudaFuncSetAttribute(gemm2_mma, cudaFuncAttributeMaxDynamicSharedMemorySize, SMEM2_TOTAL);

    init_kernel<<<1, 32>>>();
    hist_kernel<<<(N_ROWS + 255) / 256, 256>>>(dom);
    plan_kernel<<<1, 32>>>();
    scatter_kernel<<<(N_ROWS + 255) / 256, 256>>>(dom);

    dim3 grid1(MAX_TILES, D_HID / BN);   // (384, 4)
    gemm1_mma<<<grid1, NTHREADS, SMEM1_TOTAL>>>(x, W1, b1);

    gemm2_mma<<<MAX_TILES, NTHREADS, SMEM2_TOTAL>>>(W2, gamma, beta, b2, out);
}

// round 5
// speedup vs baseline: 3.0610x; 1.0943x over previous
#include <cuda_runtime.h>
#include <cuda_bf16.h>
#include <cstdint>

// ---------------- problem constants ----------------
#define N_ROWS   32768
#define D_IN     256
#define D_HID    1024
#define D_OUT    256
#define N_DOM    8
#define LN_EPS   1e-5f

#define BM 128
#define BN 256
#define BK 16
#define NTHREADS 256
#define MAX_TILES 384
#define RSA_F 20           // A smem row stride (floats), m-major 128 rows
#define RSB_F 264          // B smem row stride (floats), k-major 16 rows

#define SA_STAGE (BM * RSA_F * 4)      // 10240 B
#define SB_STAGE (BK * RSB_F * 4)      // 16896 B

// GEMM1: 4-stage A, 4-stage B
#define OFF1_A 0
#define OFF1_B (4 * SA_STAGE)                       // 40960
#define END1   (OFF1_B + 4 * SB_STAGE)              // 108544
#define G1_PERM END1
#define G1_STAT (END1 + 512)
#define SMEM1_TOTAL (END1 + 512 + 4096)             // 113152

// GEMM2: 2-slot A, 4-stage B
#define OFF2_A 0
#define OFF2_B (2 * SA_STAGE)                       // 20480
#define END2   (OFF2_B + 4 * SB_STAGE)              // 88064
#define G2_G    END2
#define G2_B    (END2 + 4096)
#define G2_MU   (END2 + 8192)
#define G2_RS   (END2 + 8704)
#define G2_PERM (END2 + 9216)
#define SMEM2_TOTAL (END2 + 9728)                   // 97792

// ---------------- device scratch ----------------
__device__ int g_count[N_DOM], g_offset[N_DOM], g_fill[N_DOM];
__device__ int g_perm[N_ROWS];
__device__ int g_tile_dom[MAX_TILES], g_tile_row[MAX_TILES], g_tile_cnt[MAX_TILES];
__device__ int g_ntiles;
__device__ __align__(16) float  g_h[(size_t)N_ROWS * D_HID];      // 128 MiB, raw h+bias
__device__ __align__(16) float2 g_part[(size_t)N_ROWS * 4];
__device__ __align__(16) float  g_xr[(size_t)N_ROWS * D_IN];      // gathered + tf32-rounded x
__device__ __align__(16) float  g_w1r[(size_t)N_DOM * D_IN * D_HID];
__device__ __align__(16) float  g_w2r[(size_t)N_DOM * D_HID * D_OUT];

// ---------------- helpers ----------------
__device__ __forceinline__ uint32_t f2tf32(float f) {
    uint32_t u;
    asm("cvt.rna.tf32.f32 %0, %1;" : "=r"(u) : "f"(f));
    return u;
}
__device__ __forceinline__ void mma8(float* c, const uint32_t* a, const uint32_t* b) {
    asm volatile("mma.sync.aligned.m16n8k8.row.col.f32.tf32.tf32.f32 "
        "{%0,%1,%2,%3}, {%4,%5,%6,%7}, {%8,%9}, {%0,%1,%2,%3};"
        : "+f"(c[0]), "+f"(c[1]), "+f"(c[2]), "+f"(c[3])
        : "r"(a[0]), "r"(a[1]), "r"(a[2]), "r"(a[3]), "r"(b[0]), "r"(b[1]));
}
#define CP16(dst, src) \
    asm volatile("cp.async.cg.shared.global [%0], [%1], 16;" :: "r"(dst), "l"(src) : "memory")
#define CP_COMMIT() asm volatile("cp.async.commit_group;" ::: "memory")
#define CP_WAIT2()  asm volatile("cp.async.wait_group 2;" ::: "memory")

// ---------------- sort/plan kernels ----------------
__global__ void init_kernel() {
    int t = threadIdx.x;
    if (t < N_DOM) { g_count[t] = 0; g_fill[t] = 0; }
}
__global__ void hist_kernel(const int* __restrict__ dom) {
    int i = blockIdx.x * blockDim.x + threadIdx.x;
    if (i < N_ROWS) atomicAdd(&g_count[dom[i]], 1);
}
__global__ void plan_kernel() {
    if (threadIdx.x == 0 && blockIdx.x == 0) {
        int off = 0, nt = 0;
        for (int d = 0; d < N_DOM; d++) {
            g_offset[d] = off;
            int c = g_count[d];
            for (int t = 0; t < c; t += BM) {
                g_tile_dom[nt] = d;
                g_tile_row[nt] = off + t;
                g_tile_cnt[nt] = min(BM, c - t);
                nt++;
            }
            off += c;
        }
        g_ntiles = nt;
    }
}
__global__ void scatter_kernel(const int* __restrict__ dom) {
    int i = blockIdx.x * blockDim.x + threadIdx.x;
    if (i < N_ROWS) {
        int d = dom[i];
        int pos = g_offset[d] + atomicAdd(&g_fill[d], 1);
        g_perm[pos] = i;
    }
}

// ---------------- pre-round kernels ----------------
__global__ void round_kernel(const float* __restrict__ src, float* __restrict__ dst, int n4) {
    int i = blockIdx.x * blockDim.x + threadIdx.x;
    if (i < n4) {
        float4 v = ((const float4*)src)[i];
        float4 o;
        o.x = __uint_as_float(f2tf32(v.x));
        o.y = __uint_as_float(f2tf32(v.y));
        o.z = __uint_as_float(f2tf32(v.z));
        o.w = __uint_as_float(f2tf32(v.w));
        ((float4*)dst)[i] = o;
    }
}
__global__ void gather_round_x(const float* __restrict__ x) {
    int i = blockIdx.x * blockDim.x + threadIdx.x;   // over 32768*64 float4
    int row = i >> 6, c = i & 63;
    int sr = g_perm[row];
    float4 v = *(const float4*)(x + (size_t)sr * D_IN + c * 4);
    float4 o;
    o.x = __uint_as_float(f2tf32(v.x));
    o.y = __uint_as_float(f2tf32(v.y));
    o.z = __uint_as_float(f2tf32(v.z));
    o.w = __uint_as_float(f2tf32(v.w));
    *(float4*)(g_xr + (size_t)row * D_IN + c * 4) = o;
}

// ---------------- fragment compute (A m-major stride RSA_F, B k-major stride RSB_F) ----------------
#define COMPUTE_FRAGS(As_, Bs_) do {                                                  \
    _Pragma("unroll")                                                                  \
    for (int kk = 0; kk < BK; kk += 8) {                                               \
        uint32_t a[4][4], b[8][2];                                                     \
        _Pragma("unroll")                                                              \
        for (int mf = 0; mf < 4; mf++) {                                               \
            const float* A_ = (As_) + (wm * 64 + mf * 16 + lm) * RSA_F + kk + lk;      \
            a[mf][0] = __float_as_uint(A_[0]);                                         \
            a[mf][1] = __float_as_uint(A_[8 * RSA_F]);                                 \
            a[mf][2] = __float_as_uint(A_[4]);                                         \
            a[mf][3] = __float_as_uint(A_[8 * RSA_F + 4]);                             \
        }                                                                              \
        const float* B_ = (Bs_) + (kk + lk) * RSB_F + wn * 64 + lm;                    \
        _Pragma("unroll")                                                              \
        for (int nf = 0; nf < 8; nf++) {                                               \
            b[nf][0] = __float_as_uint(B_[nf * 8]);                                    \
            b[nf][1] = __float_as_uint(B_[4 * RSB_F + nf * 8]);                        \
        }                                                                              \
        _Pragma("unroll")                                                              \
        for (int mf = 0; mf < 4; mf++)                                                 \
            _Pragma("unroll")                                                          \
            for (int nf = 0; nf < 8; nf++)                                             \
                mma8(acc[mf][nf], a[mf], b[nf]);                                       \
    }                                                                                  \
} while (0)

// ============================================================================
// GEMM1: h = g_xr @ W1r[d] + b1[d]; per-row (sum,sumsq) partials
// grid (MAX_TILES, 4) — CTA 128x256, K=256, full cp.async 4-stage
// ============================================================================
__global__ __launch_bounds__(NTHREADS, 1)
void gemm1_cp(const float* __restrict__ b1) {
    extern __shared__ __align__(16) char smem[];
    uint32_t sbase = (uint32_t)__cvta_generic_to_shared(smem);
    int*    sPerm = (int*)(smem + G1_PERM);
    float2* sStat = (float2*)(smem + G1_STAT);

    int bt = blockIdx.x;
    if (bt >= g_ntiles) return;
    int dom  = g_tile_dom[bt];
    int row0 = g_tile_row[bt];
    int cnt  = g_tile_cnt[bt];
    int by   = blockIdx.y;
    int colBase = by * BN;

    int tid  = threadIdx.x;
    int lane = tid & 31, wid = tid >> 5;
    int wm = wid >> 2, wn = wid & 3;
    int lk = lane & 3, lm = lane >> 2;

    if (tid < BM) sPerm[tid] = (tid < cnt) ? g_perm[row0 + tid] : -1;

    const float* W1r = g_w1r + (size_t)dom * D_IN * D_HID;

    // loader indices
    int ar0 = tid >> 2, ac = tid & 3;                 // A: rows ar0, ar0+64; 16B col ac
    int ag0 = min(row0 + ar0, N_ROWS - 1);
    int ag1 = min(row0 + ar0 + 64, N_ROWS - 1);
    int bk = tid >> 6, bc = tid & 63;                 // B: k rows bk+{0,4,8,12}; 16B col bc

    #define ISSUE1(cidx) do {                                                          \
        int k0_ = (cidx) * BK;                                                         \
        uint32_t sa = sbase + OFF1_A + ((cidx) & 3) * SA_STAGE;                        \
        uint32_t sb = sbase + OFF1_B + ((cidx) & 3) * SB_STAGE;                        \
        CP16(sa + ar0 * 80 + ac * 16,        g_xr + (size_t)ag0 * D_IN + k0_ + ac * 4);\
        CP16(sa + (ar0 + 64) * 80 + ac * 16, g_xr + (size_t)ag1 * D_IN + k0_ + ac * 4);\
        _Pragma("unroll")                                                              \
        for (int i_ = 0; i_ < 4; i_++) {                                               \
            int kr = bk + i_ * 4;                                                      \
            CP16(sb + kr * 1056 + bc * 16,                                             \
                 W1r + (size_t)(k0_ + kr) * D_HID + colBase + bc * 4);                 \
        }                                                                              \
        CP_COMMIT();                                                                   \
    } while (0)

    float acc[4][8][4];
    #pragma unroll
    for (int i = 0; i < 4; i++)
        #pragma unroll
        for (int j = 0; j < 8; j++)
            #pragma unroll
            for (int q = 0; q < 4; q++) acc[i][j][q] = 0.f;

    ISSUE1(0); ISSUE1(1); ISSUE1(2);

    const int NC = D_IN / BK;  // 16
    for (int c = 0; c < NC; c++) {
        CP_WAIT2();
        __syncthreads();
        if (c + 3 < NC) ISSUE1(c + 3); else CP_COMMIT();
        const float* Ac = (const float*)(smem + OFF1_A + (c & 3) * SA_STAGE);
        const float* Bc = (const float*)(smem + OFF1_B + (c & 3) * SB_STAGE);
        COMPUTE_FRAGS(Ac, Bc);
    }
    #undef ISSUE1

    // ---- epilogue: bias add, store h, per-row stats ----
    __syncthreads();
    const float* b1d = b1 + (size_t)dom * D_HID + colBase + wn * 64;
    #pragma unroll
    for (int mf = 0; mf < 4; mf++) {
        #pragma unroll
        for (int rsel = 0; rsel < 2; rsel++) {
            int r = wm * 64 + mf * 16 + lm + rsel * 8;
            float s = 0.f, ss = 0.f;
            float* hrow = g_h + (size_t)(row0 + r) * D_HID + colBase + wn * 64;
            bool wr = (r < cnt);
            #pragma unroll
            for (int nf = 0; nf < 8; nf++) {
                int cc = nf * 8 + 2 * lk;
                float v0 = acc[mf][nf][rsel * 2 + 0] + __ldg(b1d + cc);
                float v1 = acc[mf][nf][rsel * 2 + 1] + __ldg(b1d + cc + 1);
                s += v0 + v1;
                ss += v0 * v0 + v1 * v1;
                if (wr) *(float2*)(hrow + cc) = make_float2(v0, v1);
            }
            s  += __shfl_xor_sync(0xffffffffu, s, 1);
            s  += __shfl_xor_sync(0xffffffffu, s, 2);
            ss += __shfl_xor_sync(0xffffffffu, ss, 1);
            ss += __shfl_xor_sync(0xffffffffu, ss, 2);
            if (lk == 0) sStat[r * 4 + wn] = make_float2(s, ss);
        }
    }
    __syncthreads();
    if (tid < BM && tid < cnt) {
        float s = 0.f, ss = 0.f;
        #pragma unroll
        for (int q = 0; q < 4; q++) {
            float2 p = sStat[tid * 4 + q];
            s += p.x; ss += p.y;
        }
        g_part[(size_t)(row0 + tid) * 4 + by] = make_float2(s, ss);
    }
}

// ============================================================================
// GEMM2: out[perm] = relu(LN(h)*gamma+beta) @ W2r[d] + b2[d]
// grid (MAX_TILES) — CTA 128x256 (full D_OUT), K=1024
// A: fused LN loader (2 slots), B: cp.async 4-stage
// ============================================================================
__global__ __launch_bounds__(NTHREADS, 1)
void gemm2_cp(const float* __restrict__ gamma,
              const float* __restrict__ beta,
              const float* __restrict__ b2,
              float* __restrict__ out) {
    extern __shared__ __align__(16) char smem[];
    uint32_t sbase = (uint32_t)__cvta_generic_to_shared(smem);
    float* sG  = (float*)(smem + G2_G);
    float* sBt = (float*)(smem + G2_B);
    float* sMu = (float*)(smem + G2_MU);
    float* sRs = (float*)(smem + G2_RS);
    int*   sPerm = (int*)(smem + G2_PERM);

    int bt = blockIdx.x;
    if (bt >= g_ntiles) return;
    int dom  = g_tile_dom[bt];
    int row0 = g_tile_row[bt];
    int cnt  = g_tile_cnt[bt];

    int tid  = threadIdx.x;
    int lane = tid & 31, wid = tid >> 5;
    int wm = wid >> 2, wn = wid & 3;
    int lk = lane & 3, lm = lane >> 2;

    for (int i = tid; i < D_HID; i += NTHREADS) {
        sG[i]  = gamma[(size_t)dom * D_HID + i];
        sBt[i] = beta[(size_t)dom * D_HID + i];
    }
    if (tid < BM) {
        sPerm[tid] = (tid < cnt) ? g_perm[row0 + tid] : -1;
        float mu = 0.f, rs = 0.f;
        if (tid < cnt) {
            float s = 0.f, ss = 0.f;
            #pragma unroll
            for (int q = 0; q < 4; q++) {
                float2 p = g_part[(size_t)(row0 + tid) * 4 + q];
                s += p.x; ss += p.y;
            }
            mu = s * (1.f / D_HID);
            float var = ss * (1.f / D_HID) - mu * mu;
            rs = rsqrtf(var + LN_EPS);
        }
        sMu[tid] = mu; sRs[tid] = rs;
    }
    __syncthreads();

    const float* W2r = g_w2r + (size_t)dom * D_HID * D_OUT;

    // A loader: rows arow0, arow0+64; 16B col af4
    int arow0 = tid >> 2, af4 = tid & 3;
    int ic0 = min(arow0, cnt - 1), ic1 = min(arow0 + 64, cnt - 1);
    int ia0 = row0 + ic0, ia1 = row0 + ic1;
    float mu0 = sMu[ic0], rs0 = sRs[ic0];
    float mu1 = sMu[ic1], rs1 = sRs[ic1];
    // B loader
    int bk = tid >> 6, bc = tid & 63;

    #define ISSUE2B(cidx) do {                                                          \
        int k0_ = (cidx) * BK;                                                          \
        uint32_t sb = sbase + OFF2_B + ((cidx) & 3) * SB_STAGE;                         \
        _Pragma("unroll")                                                               \
        for (int i_ = 0; i_ < 4; i_++) {                                                \
            int kr = bk + i_ * 4;                                                       \
            CP16(sb + kr * 1056 + bc * 16,                                              \
                 W2r + (size_t)(k0_ + kr) * D_OUT + bc * 4);                            \
        }                                                                               \
        CP_COMMIT();                                                                    \
    } while (0)

    float4 pa0, pa1;
    #define LDG_A(k0_) do {                                                             \
        pa0 = *(const float4*)(g_h + (size_t)ia0 * D_HID + (k0_) + af4 * 4);            \
        pa1 = *(const float4*)(g_h + (size_t)ia1 * D_HID + (k0_) + af4 * 4);            \
    } while (0)

    #define LN4(v, mu, rs, kb) do {                                                    \
        (v).x = fmaxf(fmaf(((v).x - (mu)) * (rs), sG[(kb) + 0], sBt[(kb) + 0]), 0.f);   \
        (v).y = fmaxf(fmaf(((v).y - (mu)) * (rs), sG[(kb) + 1], sBt[(kb) + 1]), 0.f);   \
        (v).z = fmaxf(fmaf(((v).z - (mu)) * (rs), sG[(kb) + 2], sBt[(kb) + 2]), 0.f);   \
        (v).w = fmaxf(fmaf(((v).w - (mu)) * (rs), sG[(kb) + 3], sBt[(kb) + 3]), 0.f);   \
    } while (0)

    #define PREP_STS_A(slot, k0_) do {                                                  \
        LN4(pa0, mu0, rs0, (k0_) + af4 * 4);                                            \
        LN4(pa1, mu1, rs1, (k0_) + af4 * 4);                                            \
        uint4 t0, t1;                                                                   \
        t0.x = f2tf32(pa0.x); t0.y = f2tf32(pa0.y);                                     \
        t0.z = f2tf32(pa0.z); t0.w = f2tf32(pa0.w);                                     \
        t1.x = f2tf32(pa1.x); t1.y = f2tf32(pa1.y);                                     \
        t1.z = f2tf32(pa1.z); t1.w = f2tf32(pa1.w);                                     \
        char* ab = smem + OFF2_A + (slot) * SA_STAGE;                                   \
        *(uint4*)(ab + arow0 * 80 + af4 * 16) = t0;                                     \
        *(uint4*)(ab + (arow0 + 64) * 80 + af4 * 16) = t1;                              \
    } while (0)

    float acc[4][8][4];
    #pragma unroll
    for (int i = 0; i < 4; i++)
        #pragma unroll
        for (int j = 0; j < 8; j++)
            #pragma unroll
            for (int q = 0; q < 4; q++) acc[i][j][q] = 0.f;

    ISSUE2B(0); ISSUE2B(1); ISSUE2B(2);
    LDG_A(0);
    PREP_STS_A(0, 0);

    const int NC = D_HID / BK;  // 64
    for (int c = 0; c < NC; c++) {
        CP_WAIT2();
        __syncthreads();
        if (c + 3 < NC) ISSUE2B(c + 3); else CP_COMMIT();
        if (c + 1 < NC) LDG_A((c + 1) * BK);
        const float* Ac = (const float*)(smem + OFF2_A + (c & 1) * SA_STAGE);
        const float* Bc = (const float*)(smem + OFF2_B + (c & 3) * SB_STAGE);
        COMPUTE_FRAGS(Ac, Bc);
        if (c + 1 < NC) PREP_STS_A((c + 1) & 1, (c + 1) * BK);
    }
    #undef ISSUE2B
    #undef LDG_A
    #undef LN4
    #undef PREP_STS_A

    // ---- epilogue: bias add, scatter to out ----
    const float* b2d = b2 + (size_t)dom * D_OUT + wn * 64;
    #pragma unroll
    for (int mf = 0; mf < 4; mf++) {
        #pragma unroll
        for (int rsel = 0; rsel < 2; rsel++) {
            int r = wm * 64 + mf * 16 + lm + rsel * 8;
            int src = sPerm[r];
            if (src < 0) continue;
            float* orow = out + (size_t)src * D_OUT + wn * 64;
            #pragma unroll
            for (int nf = 0; nf < 8; nf++) {
                int cc = nf * 8 + 2 * lk;
                float v0 = acc[mf][nf][rsel * 2 + 0] + __ldg(b2d + cc);
                float v1 = acc[mf][nf][rsel * 2 + 1] + __ldg(b2d + cc + 1);
                *(float2*)(orow + cc) = make_float2(v0, v1);
            }
        }
    }
}

// ---------------- launch ----------------
extern "C" void kernel_launch(void* const* d_in, const int* in_sizes, int n_in,
                              void* d_out, int out_size) {
    const float* x     = (const float*)d_in[0];
    const int*   dom   = (const int*)  d_in[1];
    const float* W1    = (const float*)d_in[2];
    const float* b1    = (const float*)d_in[3];
    const float* gamma = (const float*)d_in[4];
    const float* beta  = (const float*)d_in[5];
    const float* W2    = (const float*)d_in[6];
    const float* b2    = (const float*)d_in[7];
    float* out = (float*)d_out;

    cudaFuncSetAttribute(gemm1_cp, cudaFuncAttributeMaxDynamicSharedMemorySize, SMEM1_TOTAL);
    cudaFuncSetAttribute(gemm2_cp, cudaFuncAttributeMaxDynamicSharedMemorySize, SMEM2_TOTAL);

    init_kernel<<<1, 32>>>();
    hist_kernel<<<(N_ROWS + 255) / 256, 256>>>(dom);
    plan_kernel<<<1, 32>>>();
    scatter_kernel<<<(N_ROWS + 255) / 256, 256>>>(dom);

    {   // pre-round weights and gathered x to tf32
        float* w1r; cudaGetSymbolAddress((void**)&w1r, g_w1r);
        float* w2r; cudaGetSymbolAddress((void**)&w2r, g_w2r);
        int n4w = N_DOM * D_IN * D_HID / 4;   // 524288
        round_kernel<<<n4w / 256, 256>>>(W1, w1r, n4w);
        round_kernel<<<n4w / 256, 256>>>(W2, w2r, n4w);
        int n4x = N_ROWS * D_IN / 4;          // 2097152
        gather_round_x<<<n4x / 256, 256>>>(x);
    }

    dim3 grid1(MAX_TILES, D_HID / BN);   // (384, 4)
    gemm1_cp<<<grid1, NTHREADS, SMEM1_TOTAL>>>(b1);

    gemm2_cp<<<MAX_TILES, NTHREADS, SMEM2_TOTAL>>>(gamma, beta, b2, out);
}

// round 6
// speedup vs baseline: 3.6091x; 1.1790x over previous
#include <cuda_runtime.h>
#include <cuda_fp16.h>
#include <cstdint>

// ---------------- problem constants ----------------
#define N_ROWS   32768
#define D_IN     256
#define D_HID    1024
#define D_OUT    256
#define N_DOM    8
#define LN_EPS   1e-5f

#define BM 128
#define BN 256
#define BK 32
#define NTHREADS 256
#define MAX_TILES 384
#define RSH 80             // smem row stride in BYTES (32 halfs data + 8 pad)

#define SA_ST (BM * RSH)   // 10240 B per A stage
#define SB_ST (BN * RSH)   // 20480 B per B stage

// GEMM1: 3-stage A, 3-stage B
#define OFF1_A 0
#define OFF1_B (3 * SA_ST)                        // 30720
#define END1   (OFF1_B + 3 * SB_ST)               // 92160
#define G1_PERM END1
#define G1_STAT (END1 + 512)
#define SMEM1_TOTAL (END1 + 512 + 4096)           // 96768

// GEMM2: 2-slot A, 3-stage B
#define OFF2_A 0
#define OFF2_B (2 * SA_ST)                        // 20480
#define END2   (OFF2_B + 3 * SB_ST)               // 81920
#define G2_G    END2
#define G2_B    (END2 + 4096)
#define G2_MU   (END2 + 8192)
#define G2_RS   (END2 + 8704)
#define G2_PERM (END2 + 9216)
#define SMEM2_TOTAL (END2 + 9728)                 // 91648

// ---------------- device scratch ----------------
__device__ int g_count[N_DOM], g_offset[N_DOM], g_fill[N_DOM];
__device__ int g_perm[N_ROWS];
__device__ int g_tile_dom[MAX_TILES], g_tile_row[MAX_TILES], g_tile_cnt[MAX_TILES];
__device__ int g_ntiles;
__device__ __align__(16) float  g_h[(size_t)N_ROWS * D_HID];      // fp32 h+bias (exact-ish)
__device__ __align__(16) float2 g_part[(size_t)N_ROWS * 4];
__device__ __align__(16) __half g_xh[(size_t)N_ROWS * D_IN];      // gathered fp16 x
__device__ __align__(16) __half g_w1h[(size_t)N_DOM * D_HID * D_IN];  // [d][n][k] fp16
__device__ __align__(16) __half g_w2h[(size_t)N_DOM * D_OUT * D_HID]; // [d][n][k] fp16

// ---------------- helpers ----------------
__device__ __forceinline__ void mma16(float* c, const uint32_t* a, const uint32_t* b) {
    asm volatile("mma.sync.aligned.m16n8k16.row.col.f32.f16.f16.f32 "
        "{%0,%1,%2,%3}, {%4,%5,%6,%7}, {%8,%9}, {%0,%1,%2,%3};"
        : "+f"(c[0]), "+f"(c[1]), "+f"(c[2]), "+f"(c[3])
        : "r"(a[0]), "r"(a[1]), "r"(a[2]), "r"(a[3]), "r"(b[0]), "r"(b[1]));
}
#define CP16(dst, src) \
    asm volatile("cp.async.cg.shared.global [%0], [%1], 16;" :: "r"(dst), "l"(src) : "memory")
#define CP_COMMIT() asm volatile("cp.async.commit_group;" ::: "memory")
#define CP_WAIT1()  asm volatile("cp.async.wait_group 1;" ::: "memory")

__device__ __forceinline__ uint32_t pack2(float lo, float hi) {
    __half2 h = __floats2half2_rn(lo, hi);
    return *(uint32_t*)&h;
}

// ---------------- sort/plan kernels ----------------
__global__ void init_kernel() {
    int t = threadIdx.x;
    if (t < N_DOM) { g_count[t] = 0; g_fill[t] = 0; }
}
__global__ void hist_kernel(const int* __restrict__ dom) {
    int i = blockIdx.x * blockDim.x + threadIdx.x;
    if (i < N_ROWS) atomicAdd(&g_count[dom[i]], 1);
}
__global__ void plan_kernel() {
    if (threadIdx.x == 0 && blockIdx.x == 0) {
        int off = 0, nt = 0;
        for (int d = 0; d < N_DOM; d++) {
            g_offset[d] = off;
            int c = g_count[d];
            for (int t = 0; t < c; t += BM) {
                g_tile_dom[nt] = d;
                g_tile_row[nt] = off + t;
                g_tile_cnt[nt] = min(BM, c - t);
                nt++;
            }
            off += c;
        }
        g_ntiles = nt;
    }
}
__global__ void scatter_kernel(const int* __restrict__ dom) {
    int i = blockIdx.x * blockDim.x + threadIdx.x;
    if (i < N_ROWS) {
        int d = dom[i];
        int pos = g_offset[d] + atomicAdd(&g_fill[d], 1);
        g_perm[pos] = i;
    }
}

// ---------------- pre-transform kernels ----------------
// transpose+convert: src [z][K][N] f32 -> dst [z][N][K] fp16
__global__ void transp_h(const float* __restrict__ src, __half* __restrict__ dst,
                         int K, int N) {
    __shared__ float t[32][33];
    int z = blockIdx.z;
    const float* s = src + (size_t)z * K * N;
    __half* d = dst + (size_t)z * K * N;
    int n0 = blockIdx.x * 32, k0 = blockIdx.y * 32;
    #pragma unroll
    for (int i = threadIdx.y; i < 32; i += 8)
        t[i][threadIdx.x] = s[(size_t)(k0 + i) * N + n0 + threadIdx.x];
    __syncthreads();
    #pragma unroll
    for (int i = threadIdx.y; i < 32; i += 8)
        d[(size_t)(n0 + i) * K + k0 + threadIdx.x] = __float2half_rn(t[threadIdx.x][i]);
}
// gather + convert x: g_xh[row] = fp16(x[perm[row]])
__global__ void gather_x_h(const float* __restrict__ x) {
    int i = blockIdx.x * blockDim.x + threadIdx.x;   // N_ROWS * 32 chunks of 8 halfs
    int row = i >> 5, c = i & 31;
    const float* src = x + (size_t)g_perm[row] * D_IN + c * 8;
    float4 v0 = *(const float4*)(src);
    float4 v1 = *(const float4*)(src + 4);
    uint4 o;
    o.x = pack2(v0.x, v0.y); o.y = pack2(v0.z, v0.w);
    o.z = pack2(v1.x, v1.y); o.w = pack2(v1.z, v1.w);
    *(uint4*)(g_xh + (size_t)row * D_IN + c * 8) = o;
}

// ---------------- fragment compute (A [m][k] halfs, B [n][k] halfs, stride RSH bytes) ----------------
#define COMPUTE_FRAGS(As_, Bs_) do {                                                  \
    _Pragma("unroll")                                                                  \
    for (int kk = 0; kk < BK; kk += 16) {                                              \
        uint32_t a[4][4], b[8][2];                                                     \
        _Pragma("unroll")                                                              \
        for (int mf = 0; mf < 4; mf++) {                                               \
            const char* A_ = (As_) + (wm * 64 + mf * 16 + lm) * RSH + (kk + lk * 2) * 2; \
            a[mf][0] = *(const uint32_t*)(A_);                                         \
            a[mf][1] = *(const uint32_t*)(A_ + 8 * RSH);                               \
            a[mf][2] = *(const uint32_t*)(A_ + 16);                                    \
            a[mf][3] = *(const uint32_t*)(A_ + 8 * RSH + 16);                          \
        }                                                                              \
        _Pragma("unroll")                                                              \
        for (int nf = 0; nf < 8; nf++) {                                               \
            const char* B_ = (Bs_) + (wn * 64 + nf * 8 + lm) * RSH + (kk + lk * 2) * 2; \
            b[nf][0] = *(const uint32_t*)(B_);                                         \
            b[nf][1] = *(const uint32_t*)(B_ + 16);                                    \
        }                                                                              \
        _Pragma("unroll")                                                              \
        for (int mf = 0; mf < 4; mf++)                                                 \
            _Pragma("unroll")                                                          \
            for (int nf = 0; nf < 8; nf++)                                             \
                mma16(acc[mf][nf], a[mf], b[nf]);                                      \
    }                                                                                  \
} while (0)

// ============================================================================
// GEMM1: h = g_xh @ W1h[d]^T + b1; per-row (sum,sumsq) partials
// grid (MAX_TILES, 4) — CTA 128x256, K=256, 3-stage cp.async
// ============================================================================
__global__ __launch_bounds__(NTHREADS, 1)
void gemm1_h(const float* __restrict__ b1) {
    extern __shared__ __align__(16) char smem[];
    uint32_t sbase = (uint32_t)__cvta_generic_to_shared(smem);
    int*    sPerm = (int*)(smem + G1_PERM);
    float2* sStat = (float2*)(smem + G1_STAT);

    int bt = blockIdx.x;
    if (bt >= g_ntiles) return;
    int dom  = g_tile_dom[bt];
    int row0 = g_tile_row[bt];
    int cnt  = g_tile_cnt[bt];
    int by   = blockIdx.y;
    int colBase = by * BN;

    int tid  = threadIdx.x;
    int lane = tid & 31, wid = tid >> 5;
    int wm = wid >> 2, wn = wid & 3;
    int lk = lane & 3, lm = lane >> 2;

    if (tid < BM) sPerm[tid] = (tid < cnt) ? g_perm[row0 + tid] : -1;

    const __half* W1h = g_w1h + ((size_t)dom * D_HID + colBase) * D_IN;

    // A loader: row = tid>>1, two 16B chunks at (tid&1)*2 + {0,1}
    int arow = tid >> 1, ach = (tid & 1) * 2;
    int agr = min(row0 + arow, N_ROWS - 1);
    // B loader: n = tid, 4 x 16B along k
    int bn = tid;

    #define ISSUE1(cidx) do {                                                          \
        int k0_ = (cidx) * BK;                                                         \
        uint32_t sa = sbase + OFF1_A + ((cidx) % 3) * SA_ST;                           \
        uint32_t sb = sbase + OFF1_B + ((cidx) % 3) * SB_ST;                           \
        CP16(sa + arow * RSH + ach * 16,       g_xh + (size_t)agr * D_IN + k0_ + ach * 8); \
        CP16(sa + arow * RSH + (ach + 1) * 16, g_xh + (size_t)agr * D_IN + k0_ + (ach + 1) * 8); \
        const __half* bsrc = W1h + (size_t)bn * D_IN + k0_;                            \
        _Pragma("unroll")                                                              \
        for (int j_ = 0; j_ < 4; j_++)                                                 \
            CP16(sb + bn * RSH + j_ * 16, bsrc + j_ * 8);                              \
        CP_COMMIT();                                                                   \
    } while (0)

    float acc[4][8][4];
    #pragma unroll
    for (int i = 0; i < 4; i++)
        #pragma unroll
        for (int j = 0; j < 8; j++)
            #pragma unroll
            for (int q = 0; q < 4; q++) acc[i][j][q] = 0.f;

    ISSUE1(0); ISSUE1(1);

    const int NC = D_IN / BK;  // 8
    for (int c = 0; c < NC; c++) {
        CP_WAIT1();
        __syncthreads();
        if (c + 2 < NC) ISSUE1(c + 2); else CP_COMMIT();
        const char* Ac = smem + OFF1_A + (c % 3) * SA_ST;
        const char* Bc = smem + OFF1_B + (c % 3) * SB_ST;
        COMPUTE_FRAGS(Ac, Bc);
    }
    #undef ISSUE1

    // ---- epilogue: bias add, store h, per-row stats ----
    __syncthreads();
    const float* b1d = b1 + (size_t)dom * D_HID + colBase + wn * 64;
    #pragma unroll
    for (int mf = 0; mf < 4; mf++) {
        #pragma unroll
        for (int rsel = 0; rsel < 2; rsel++) {
            int r = wm * 64 + mf * 16 + lm + rsel * 8;
            float s = 0.f, ss = 0.f;
            float* hrow = g_h + (size_t)(row0 + r) * D_HID + colBase + wn * 64;
            bool wr = (r < cnt);
            #pragma unroll
            for (int nf = 0; nf < 8; nf++) {
                int cc = nf * 8 + 2 * lk;
                float v0 = acc[mf][nf][rsel * 2 + 0] + __ldg(b1d + cc);
                float v1 = acc[mf][nf][rsel * 2 + 1] + __ldg(b1d + cc + 1);
                s += v0 + v1;
                ss += v0 * v0 + v1 * v1;
                if (wr) *(float2*)(hrow + cc) = make_float2(v0, v1);
            }
            s  += __shfl_xor_sync(0xffffffffu, s, 1);
            s  += __shfl_xor_sync(0xffffffffu, s, 2);
            ss += __shfl_xor_sync(0xffffffffu, ss, 1);
            ss += __shfl_xor_sync(0xffffffffu, ss, 2);
            if (lk == 0) sStat[r * 4 + wn] = make_float2(s, ss);
        }
    }
    __syncthreads();
    if (tid < BM && tid < cnt) {
        float s = 0.f, ss = 0.f;
        #pragma unroll
        for (int q = 0; q < 4; q++) {
            float2 p = sStat[tid * 4 + q];
            s += p.x; ss += p.y;
        }
        g_part[(size_t)(row0 + tid) * 4 + by] = make_float2(s, ss);
    }
}

// ============================================================================
// GEMM2: out[perm] = relu(LN(h)*gamma+beta) @ W2h[d]^T + b2
// grid (MAX_TILES) — CTA 128x256 (full D_OUT), K=1024
// A: fused LN loader (2 slots, fp16 STS), B: 3-stage cp.async
// ============================================================================
__global__ __launch_bounds__(NTHREADS, 1)
void gemm2_h(const float* __restrict__ gamma,
             const float* __restrict__ beta,
             const float* __restrict__ b2,
             float* __restrict__ out) {
    extern __shared__ __align__(16) char smem[];
    uint32_t sbase = (uint32_t)__cvta_generic_to_shared(smem);
    float* sG  = (float*)(smem + G2_G);
    float* sBt = (float*)(smem + G2_B);
    float* sMu = (float*)(smem + G2_MU);
    float* sRs = (float*)(smem + G2_RS);
    int*   sPerm = (int*)(smem + G2_PERM);

    int bt = blockIdx.x;
    if (bt >= g_ntiles) return;
    int dom  = g_tile_dom[bt];
    int row0 = g_tile_row[bt];
    int cnt  = g_tile_cnt[bt];

    int tid  = threadIdx.x;
    int lane = tid & 31, wid = tid >> 5;
    int wm = wid >> 2, wn = wid & 3;
    int lk = lane & 3, lm = lane >> 2;

    for (int i = tid; i < D_HID; i += NTHREADS) {
        sG[i]  = gamma[(size_t)dom * D_HID + i];
        sBt[i] = beta[(size_t)dom * D_HID + i];
    }
    if (tid < BM) {
        sPerm[tid] = (tid < cnt) ? g_perm[row0 + tid] : -1;
        float mu = 0.f, rs = 0.f;
        if (tid < cnt) {
            float s = 0.f, ss = 0.f;
            #pragma unroll
            for (int q = 0; q < 4; q++) {
                float2 p = g_part[(size_t)(row0 + tid) * 4 + q];
                s += p.x; ss += p.y;
            }
            mu = s * (1.f / D_HID);
            float var = ss * (1.f / D_HID) - mu * mu;
            rs = rsqrtf(var + LN_EPS);
        }
        sMu[tid] = mu; sRs[tid] = rs;
    }
    __syncthreads();

    const __half* W2h = g_w2h + (size_t)dom * D_OUT * D_HID;

    // A loader: row = tid>>1, 16 halfs at (tid&1)*16
    int arow = tid >> 1, ahalf = (tid & 1) * 16;
    int icl = min(arow, cnt - 1);
    int iar = row0 + icl;
    float amu = sMu[icl], ars = sRs[icl];
    // B loader: n = tid, 8 x 16B along k (BK=32 halfs = 64B -> 4 chunks)
    int bn = tid;

    #define ISSUE2B(cidx) do {                                                          \
        int k0_ = (cidx) * BK;                                                          \
        uint32_t sb = sbase + OFF2_B + ((cidx) % 3) * SB_ST;                            \
        const __half* bsrc = W2h + (size_t)bn * D_HID + k0_;                            \
        _Pragma("unroll")                                                               \
        for (int j_ = 0; j_ < 4; j_++)                                                  \
            CP16(sb + bn * RSH + j_ * 16, bsrc + j_ * 8);                               \
        CP_COMMIT();                                                                    \
    } while (0)

    float4 pv0, pv1, pv2, pv3;
    #define LDG_A(k0_) do {                                                             \
        const float* hsrc = g_h + (size_t)iar * D_HID + (k0_) + ahalf;                  \
        pv0 = *(const float4*)(hsrc);                                                   \
        pv1 = *(const float4*)(hsrc + 4);                                               \
        pv2 = *(const float4*)(hsrc + 8);                                               \
        pv3 = *(const float4*)(hsrc + 12);                                              \
    } while (0)

    #define LN1(f, kb) fmaxf(fmaf(((f) - amu) * ars, sG[kb], sBt[kb]), 0.f)

    #define PREP_STS_A(slot, k0_) do {                                                  \
        int kb = (k0_) + ahalf;                                                         \
        uint4 o0, o1;                                                                   \
        o0.x = pack2(LN1(pv0.x, kb+0),  LN1(pv0.y, kb+1));                              \
        o0.y = pack2(LN1(pv0.z, kb+2),  LN1(pv0.w, kb+3));                              \
        o0.z = pack2(LN1(pv1.x, kb+4),  LN1(pv1.y, kb+5));                              \
        o0.w = pack2(LN1(pv1.z, kb+6),  LN1(pv1.w, kb+7));                              \
        o1.x = pack2(LN1(pv2.x, kb+8),  LN1(pv2.y, kb+9));                              \
        o1.y = pack2(LN1(pv2.z, kb+10), LN1(pv2.w, kb+11));                             \
        o1.z = pack2(LN1(pv3.x, kb+12), LN1(pv3.y, kb+13));                             \
        o1.w = pack2(LN1(pv3.z, kb+14), LN1(pv3.w, kb+15));                             \
        char* ab = smem + OFF2_A + (slot) * SA_ST + arow * RSH + ahalf * 2;             \
        *(uint4*)(ab) = o0;                                                             \
        *(uint4*)(ab + 16) = o1;                                                        \
    } while (0)

    float acc[4][8][4];
    #pragma unroll
    for (int i = 0; i < 4; i++)
        #pragma unroll
        for (int j = 0; j < 8; j++)
            #pragma unroll
            for (int q = 0; q < 4; q++) acc[i][j][q] = 0.f;

    ISSUE2B(0); ISSUE2B(1);
    LDG_A(0);
    PREP_STS_A(0, 0);

    const int NC = D_HID / BK;  // 32
    for (int c = 0; c < NC; c++) {
        CP_WAIT1();
        __syncthreads();
        if (c + 2 < NC) ISSUE2B(c + 2); else CP_COMMIT();
        if (c + 1 < NC) LDG_A((c + 1) * BK);
        const char* Ac = smem + OFF2_A + (c & 1) * SA_ST;
        const char* Bc = smem + OFF2_B + (c % 3) * SB_ST;
        COMPUTE_FRAGS(Ac, Bc);
        if (c + 1 < NC) PREP_STS_A((c + 1) & 1, (c + 1) * BK);
    }
    #undef ISSUE2B
    #undef LDG_A
    #undef LN1
    #undef PREP_STS_A

    // ---- epilogue: bias add, scatter to out ----
    const float* b2d = b2 + (size_t)dom * D_OUT + wn * 64;
    #pragma unroll
    for (int mf = 0; mf < 4; mf++) {
        #pragma unroll
        for (int rsel = 0; rsel < 2; rsel++) {
            int r = wm * 64 + mf * 16 + lm + rsel * 8;
            int src = sPerm[r];
            if (src < 0) continue;
            float* orow = out + (size_t)src * D_OUT + wn * 64;
            #pragma unroll
            for (int nf = 0; nf < 8; nf++) {
                int cc = nf * 8 + 2 * lk;
                float v0 = acc[mf][nf][rsel * 2 + 0] + __ldg(b2d + cc);
                float v1 = acc[mf][nf][rsel * 2 + 1] + __ldg(b2d + cc + 1);
                *(float2*)(orow + cc) = make_float2(v0, v1);
            }
        }
    }
}

// ---------------- launch ----------------
extern "C" void kernel_launch(void* const* d_in, const int* in_sizes, int n_in,
                              void* d_out, int out_size) {
    const float* x     = (const float*)d_in[0];
    const int*   dom   = (const int*)  d_in[1];
    const float* W1    = (const float*)d_in[2];
    const float* b1    = (const float*)d_in[3];
    const float* gamma = (const float*)d_in[4];
    const float* beta  = (const float*)d_in[5];
    const float* W2    = (const float*)d_in[6];
    const float* b2    = (const float*)d_in[7];
    float* out = (float*)d_out;

    cudaFuncSetAttribute(gemm1_h, cudaFuncAttributeMaxDynamicSharedMemorySize, SMEM1_TOTAL);
    cudaFuncSetAttribute(gemm2_h, cudaFuncAttributeMaxDynamicSharedMemorySize, SMEM2_TOTAL);

    init_kernel<<<1, 32>>>();
    hist_kernel<<<(N_ROWS + 255) / 256, 256>>>(dom);
    plan_kernel<<<1, 32>>>();
    scatter_kernel<<<(N_ROWS + 255) / 256, 256>>>(dom);

    {   // weights: transpose + fp16; x: gather + fp16
        __half* w1h; cudaGetSymbolAddress((void**)&w1h, g_w1h);
        __half* w2h; cudaGetSymbolAddress((void**)&w2h, g_w2h);
        dim3 blk(32, 8);
        dim3 t1(D_HID / 32, D_IN / 32, N_DOM);    // (32, 8, 8)
        transp_h<<<t1, blk>>>(W1, w1h, D_IN, D_HID);
        dim3 t2(D_OUT / 32, D_HID / 32, N_DOM);   // (8, 32, 8)
        transp_h<<<t2, blk>>>(W2, w2h, D_HID, D_OUT);
        int nthr = N_ROWS * 32;                   // 1048576
        gather_x_h<<<nthr / 256, 256>>>(x);
    }

    dim3 grid1(MAX_TILES, D_HID / BN);   // (384, 4)
    gemm1_h<<<grid1, NTHREADS, SMEM1_TOTAL>>>(b1);

    gemm2_h<<<MAX_TILES, NTHREADS, SMEM2_TOTAL>>>(gamma, beta, b2, out);
}

// round 7
// speedup vs baseline: 3.9716x; 1.1005x over previous
#include <cuda_runtime.h>
#include <cuda_fp16.h>
#include <cstdint>

// ---------------- problem constants ----------------
#define N_ROWS   32768
#define D_IN     256
#define D_HID    1024
#define D_OUT    256
#define N_DOM    8
#define LN_EPS   1e-5f

#define BM 128
#define BN 256
#define BK 32
#define NTHREADS 256
#define MAX_TILES 384
#define RSH 80             // smem row stride in BYTES (32 halfs data + 8 pad)

#define SA_ST (BM * RSH)   // 10240 B per A stage
#define SB_ST (BN * RSH)   // 20480 B per B stage

// GEMM1: 3-stage A, 3-stage B
#define OFF1_A 0
#define OFF1_B (3 * SA_ST)                        // 30720
#define END1   (OFF1_B + 3 * SB_ST)               // 92160
#define G1_PERM END1
#define G1_STAT (END1 + 512)
#define SMEM1_TOTAL (END1 + 512 + 4096)           // 96768

// GEMM2: 2-slot A, 3-stage B
#define OFF2_A 0
#define OFF2_B (2 * SA_ST)                        // 20480
#define END2   (OFF2_B + 3 * SB_ST)               // 81920
#define G2_G    END2
#define G2_B    (END2 + 4096)
#define G2_MU   (END2 + 8192)
#define G2_RS   (END2 + 8704)
#define G2_PERM (END2 + 9216)
#define SMEM2_TOTAL (END2 + 9728)                 // 91648

// ---------------- device scratch ----------------
__device__ int g_count[N_DOM], g_offset[N_DOM], g_fill[N_DOM];
__device__ int g_perm[N_ROWS];
__device__ int g_tile_dom[MAX_TILES], g_tile_row[MAX_TILES], g_tile_cnt[MAX_TILES];
__device__ int g_ntiles;
__device__ __align__(16) __half g_hh[(size_t)N_ROWS * D_HID];     // fp16 h+bias (64 MiB)
__device__ __align__(16) float2 g_part[(size_t)N_ROWS * 4];
__device__ __align__(16) __half g_xh[(size_t)N_ROWS * D_IN];      // gathered fp16 x
__device__ __align__(16) __half g_w1h[(size_t)N_DOM * D_HID * D_IN];  // [d][n][k] fp16
__device__ __align__(16) __half g_w2h[(size_t)N_DOM * D_OUT * D_HID]; // [d][n][k] fp16

// ---------------- helpers ----------------
__device__ __forceinline__ void mma16(float* c, const uint32_t* a, const uint32_t* b) {
    asm volatile("mma.sync.aligned.m16n8k16.row.col.f32.f16.f16.f32 "
        "{%0,%1,%2,%3}, {%4,%5,%6,%7}, {%8,%9}, {%0,%1,%2,%3};"
        : "+f"(c[0]), "+f"(c[1]), "+f"(c[2]), "+f"(c[3])
        : "r"(a[0]), "r"(a[1]), "r"(a[2]), "r"(a[3]), "r"(b[0]), "r"(b[1]));
}
#define CP16(dst, src) \
    asm volatile("cp.async.cg.shared.global [%0], [%1], 16;" :: "r"(dst), "l"(src) : "memory")
#define CP_COMMIT() asm volatile("cp.async.commit_group;" ::: "memory")
#define CP_WAIT1()  asm volatile("cp.async.wait_group 1;" ::: "memory")

__device__ __forceinline__ uint32_t pack2(float lo, float hi) {
    __half2 h = __floats2half2_rn(lo, hi);
    return *(uint32_t*)&h;
}

// ---------------- sort/plan kernels ----------------
__global__ void init_kernel() {
    int t = threadIdx.x;
    if (t < N_DOM) { g_count[t] = 0; g_fill[t] = 0; }
}
__global__ void hist_kernel(const int* __restrict__ dom) {
    __shared__ int cnt[N_DOM];
    int t = threadIdx.x;
    if (t < N_DOM) cnt[t] = 0;
    __syncthreads();
    int i = blockIdx.x * blockDim.x + t;
    atomicAdd(&cnt[dom[i]], 1);
    __syncthreads();
    if (t < N_DOM && cnt[t] > 0) atomicAdd(&g_count[t], cnt[t]);
}
__global__ void plan_kernel() {
    if (threadIdx.x == 0 && blockIdx.x == 0) {
        int off = 0, nt = 0;
        for (int d = 0; d < N_DOM; d++) {
            g_offset[d] = off;
            int c = g_count[d];
            for (int t = 0; t < c; t += BM) {
                g_tile_dom[nt] = d;
                g_tile_row[nt] = off + t;
                g_tile_cnt[nt] = min(BM, c - t);
                nt++;
            }
            off += c;
        }
        g_ntiles = nt;
    }
}
__global__ void scatter_kernel(const int* __restrict__ dom) {
    __shared__ int cnt[N_DOM], base[N_DOM];
    int t = threadIdx.x;
    if (t < N_DOM) cnt[t] = 0;
    __syncthreads();
    int i = blockIdx.x * blockDim.x + t;
    int d = dom[i];
    int r = atomicAdd(&cnt[d], 1);
    __syncthreads();
    if (t < N_DOM && cnt[t] > 0) base[t] = atomicAdd(&g_fill[t], cnt[t]);
    __syncthreads();
    g_perm[g_offset[d] + base[d] + r] = i;
}

// ---------------- pre-transform kernels ----------------
// transpose+convert: src [z][K][N] f32 -> dst [z][N][K] fp16
__global__ void transp_h(const float* __restrict__ src, __half* __restrict__ dst,
                         int K, int N) {
    __shared__ float t[32][33];
    int z = blockIdx.z;
    const float* s = src + (size_t)z * K * N;
    __half* d = dst + (size_t)z * K * N;
    int n0 = blockIdx.x * 32, k0 = blockIdx.y * 32;
    #pragma unroll
    for (int i = threadIdx.y; i < 32; i += 8)
        t[i][threadIdx.x] = s[(size_t)(k0 + i) * N + n0 + threadIdx.x];
    __syncthreads();
    #pragma unroll
    for (int i = threadIdx.y; i < 32; i += 8)
        d[(size_t)(n0 + i) * K + k0 + threadIdx.x] = __float2half_rn(t[threadIdx.x][i]);
}
// gather + convert x: g_xh[row] = fp16(x[perm[row]])
__global__ void gather_x_h(const float* __restrict__ x) {
    int i = blockIdx.x * blockDim.x + threadIdx.x;   // N_ROWS * 32 chunks of 8 halfs
    int row = i >> 5, c = i & 31;
    const float* src = x + (size_t)g_perm[row] * D_IN + c * 8;
    float4 v0 = *(const float4*)(src);
    float4 v1 = *(const float4*)(src + 4);
    uint4 o;
    o.x = pack2(v0.x, v0.y); o.y = pack2(v0.z, v0.w);
    o.z = pack2(v1.x, v1.y); o.w = pack2(v1.z, v1.w);
    *(uint4*)(g_xh + (size_t)row * D_IN + c * 8) = o;
}

// ---------------- fragment compute (A [m][k] halfs, B [n][k] halfs, stride RSH bytes) ----------------
#define COMPUTE_FRAGS(As_, Bs_) do {                                                  \
    _Pragma("unroll")                                                                  \
    for (int kk = 0; kk < BK; kk += 16) {                                              \
        uint32_t a[4][4], b[8][2];                                                     \
        _Pragma("unroll")                                                              \
        for (int mf = 0; mf < 4; mf++) {                                               \
            const char* A_ = (As_) + (wm * 64 + mf * 16 + lm) * RSH + (kk + lk * 2) * 2; \
            a[mf][0] = *(const uint32_t*)(A_);                                         \
            a[mf][1] = *(const uint32_t*)(A_ + 8 * RSH);                               \
            a[mf][2] = *(const uint32_t*)(A_ + 16);                                    \
            a[mf][3] = *(const uint32_t*)(A_ + 8 * RSH + 16);                          \
        }                                                                              \
        _Pragma("unroll")                                                              \
        for (int nf = 0; nf < 8; nf++) {                                               \
            const char* B_ = (Bs_) + (wn * 64 + nf * 8 + lm) * RSH + (kk + lk * 2) * 2; \
            b[nf][0] = *(const uint32_t*)(B_);                                         \
            b[nf][1] = *(const uint32_t*)(B_ + 16);                                    \
        }                                                                              \
        _Pragma("unroll")                                                              \
        for (int mf = 0; mf < 4; mf++)                                                 \
            _Pragma("unroll")                                                          \
            for (int nf = 0; nf < 8; nf++)                                             \
                mma16(acc[mf][nf], a[mf], b[nf]);                                      \
    }                                                                                  \
} while (0)

// ============================================================================
// GEMM1: h = g_xh @ W1h[d]^T + b1 -> fp16 g_hh; per-row (sum,sumsq) partials
// ============================================================================
__global__ __launch_bounds__(NTHREADS, 1)
void gemm1_h(const float* __restrict__ b1) {
    extern __shared__ __align__(16) char smem[];
    uint32_t sbase = (uint32_t)__cvta_generic_to_shared(smem);
    int*    sPerm = (int*)(smem + G1_PERM);
    float2* sStat = (float2*)(smem + G1_STAT);

    int bt = blockIdx.x;
    if (bt >= g_ntiles) return;
    int dom  = g_tile_dom[bt];
    int row0 = g_tile_row[bt];
    int cnt  = g_tile_cnt[bt];
    int by   = blockIdx.y;
    int colBase = by * BN;

    int tid  = threadIdx.x;
    int lane = tid & 31, wid = tid >> 5;
    int wm = wid >> 2, wn = wid & 3;
    int lk = lane & 3, lm = lane >> 2;

    if (tid < BM) sPerm[tid] = (tid < cnt) ? g_perm[row0 + tid] : -1;

    const __half* W1h = g_w1h + ((size_t)dom * D_HID + colBase) * D_IN;

    int arow = tid >> 1, ach = (tid & 1) * 2;
    int agr = min(row0 + arow, N_ROWS - 1);
    int bn = tid;

    #define ISSUE1(cidx) do {                                                          \
        int k0_ = (cidx) * BK;                                                         \
        uint32_t sa = sbase + OFF1_A + ((cidx) % 3) * SA_ST;                           \
        uint32_t sb = sbase + OFF1_B + ((cidx) % 3) * SB_ST;                           \
        CP16(sa + arow * RSH + ach * 16,       g_xh + (size_t)agr * D_IN + k0_ + ach * 8); \
        CP16(sa + arow * RSH + (ach + 1) * 16, g_xh + (size_t)agr * D_IN + k0_ + (ach + 1) * 8); \
        const __half* bsrc = W1h + (size_t)bn * D_IN + k0_;                            \
        _Pragma("unroll")                                                              \
        for (int j_ = 0; j_ < 4; j_++)                                                 \
            CP16(sb + bn * RSH + j_ * 16, bsrc + j_ * 8);                              \
        CP_COMMIT();                                                                   \
    } while (0)

    float acc[4][8][4];
    #pragma unroll
    for (int i = 0; i < 4; i++)
        #pragma unroll
        for (int j = 0; j < 8; j++)
            #pragma unroll
            for (int q = 0; q < 4; q++) acc[i][j][q] = 0.f;

    ISSUE1(0); ISSUE1(1);

    const int NC = D_IN / BK;  // 8
    for (int c = 0; c < NC; c++) {
        CP_WAIT1();
        __syncthreads();
        if (c + 2 < NC) ISSUE1(c + 2); else CP_COMMIT();
        const char* Ac = smem + OFF1_A + (c % 3) * SA_ST;
        const char* Bc = smem + OFF1_B + (c % 3) * SB_ST;
        COMPUTE_FRAGS(Ac, Bc);
    }
    #undef ISSUE1

    // ---- epilogue: bias add, store fp16 h, per-row stats ----
    __syncthreads();
    const float* b1d = b1 + (size_t)dom * D_HID + colBase + wn * 64;
    #pragma unroll
    for (int mf = 0; mf < 4; mf++) {
        #pragma unroll
        for (int rsel = 0; rsel < 2; rsel++) {
            int r = wm * 64 + mf * 16 + lm + rsel * 8;
            float s = 0.f, ss = 0.f;
            __half* hrow = g_hh + (size_t)(row0 + r) * D_HID + colBase + wn * 64;
            bool wr = (r < cnt);
            #pragma unroll
            for (int nf = 0; nf < 8; nf++) {
                int cc = nf * 8 + 2 * lk;
                float v0 = acc[mf][nf][rsel * 2 + 0] + __ldg(b1d + cc);
                float v1 = acc[mf][nf][rsel * 2 + 1] + __ldg(b1d + cc + 1);
                s += v0 + v1;
                ss += v0 * v0 + v1 * v1;
                if (wr) *(uint32_t*)(hrow + cc) = pack2(v0, v1);
            }
            s  += __shfl_xor_sync(0xffffffffu, s, 1);
            s  += __shfl_xor_sync(0xffffffffu, s, 2);
            ss += __shfl_xor_sync(0xffffffffu, ss, 1);
            ss += __shfl_xor_sync(0xffffffffu, ss, 2);
            if (lk == 0) sStat[r * 4 + wn] = make_float2(s, ss);
        }
    }
    __syncthreads();
    if (tid < BM && tid < cnt) {
        float s = 0.f, ss = 0.f;
        #pragma unroll
        for (int q = 0; q < 4; q++) {
            float2 p = sStat[tid * 4 + q];
            s += p.x; ss += p.y;
        }
        g_part[(size_t)(row0 + tid) * 4 + by] = make_float2(s, ss);
    }
}

// ============================================================================
// GEMM2: out[perm] = relu(LN(h)*gamma+beta) @ W2h[d]^T + b2
// A: fused LN loader from fp16 g_hh (2 slots), B: 3-stage cp.async
// ============================================================================
__global__ __launch_bounds__(NTHREADS, 1)
void gemm2_h(const float* __restrict__ gamma,
             const float* __restrict__ beta,
             const float* __restrict__ b2,
             float* __restrict__ out) {
    extern __shared__ __align__(16) char smem[];
    uint32_t sbase = (uint32_t)__cvta_generic_to_shared(smem);
    float* sG  = (float*)(smem + G2_G);
    float* sBt = (float*)(smem + G2_B);
    float* sMu = (float*)(smem + G2_MU);
    float* sRs = (float*)(smem + G2_RS);
    int*   sPerm = (int*)(smem + G2_PERM);

    int bt = blockIdx.x;
    if (bt >= g_ntiles) return;
    int dom  = g_tile_dom[bt];
    int row0 = g_tile_row[bt];
    int cnt  = g_tile_cnt[bt];

    int tid  = threadIdx.x;
    int lane = tid & 31, wid = tid >> 5;
    int wm = wid >> 2, wn = wid & 3;
    int lk = lane & 3, lm = lane >> 2;

    for (int i = tid; i < D_HID; i += NTHREADS) {
        sG[i]  = gamma[(size_t)dom * D_HID + i];
        sBt[i] = beta[(size_t)dom * D_HID + i];
    }
    if (tid < BM) {
        sPerm[tid] = (tid < cnt) ? g_perm[row0 + tid] : -1;
        float mu = 0.f, rs = 0.f;
        if (tid < cnt) {
            float s = 0.f, ss = 0.f;
            #pragma unroll
            for (int q = 0; q < 4; q++) {
                float2 p = g_part[(size_t)(row0 + tid) * 4 + q];
                s += p.x; ss += p.y;
            }
            mu = s * (1.f / D_HID);
            float var = ss * (1.f / D_HID) - mu * mu;
            rs = rsqrtf(var + LN_EPS);
        }
        sMu[tid] = mu; sRs[tid] = rs;
    }
    __syncthreads();

    const __half* W2h = g_w2h + (size_t)dom * D_OUT * D_HID;

    // A loader: row = tid>>1, 16 halfs at (tid&1)*16
    int arow = tid >> 1, ahalf = (tid & 1) * 16;
    int icl = min(arow, cnt - 1);
    int iar = row0 + icl;
    float amu = sMu[icl], ars = sRs[icl];
    int bn = tid;

    #define ISSUE2B(cidx) do {                                                          \
        int k0_ = (cidx) * BK;                                                          \
        uint32_t sb = sbase + OFF2_B + ((cidx) % 3) * SB_ST;                            \
        const __half* bsrc = W2h + (size_t)bn * D_HID + k0_;                            \
        _Pragma("unroll")                                                               \
        for (int j_ = 0; j_ < 4; j_++)                                                  \
            CP16(sb + bn * RSH + j_ * 16, bsrc + j_ * 8);                               \
        CP_COMMIT();                                                                    \
    } while (0)

    uint4 h0, h1;
    #define LDG_A(k0_) do {                                                             \
        const __half* hsrc = g_hh + (size_t)iar * D_HID + (k0_) + ahalf;                \
        h0 = *(const uint4*)(hsrc);                                                     \
        h1 = *(const uint4*)(hsrc + 8);                                                 \
    } while (0)

    #define LN1(f, kb) fmaxf(fmaf(((f) - amu) * ars, sG[kb], sBt[kb]), 0.f)

    #define PREP_STS_A(slot, k0_) do {                                                  \
        int kb = (k0_) + ahalf;                                                         \
        uint32_t hw[8];                                                                 \
        hw[0] = h0.x; hw[1] = h0.y; hw[2] = h0.z; hw[3] = h0.w;                         \
        hw[4] = h1.x; hw[5] = h1.y; hw[6] = h1.z; hw[7] = h1.w;                         \
        uint32_t ow[8];                                                                 \
        _Pragma("unroll")                                                               \
        for (int j_ = 0; j_ < 8; j_++) {                                                \
            float2 f = __half22float2(*(__half2*)&hw[j_]);                              \
            ow[j_] = pack2(LN1(f.x, kb + 2 * j_), LN1(f.y, kb + 2 * j_ + 1));           \
        }                                                                               \
        char* ab = smem + OFF2_A + (slot) * SA_ST + arow * RSH + ahalf * 2;             \
        *(uint4*)(ab)      = make_uint4(ow[0], ow[1], ow[2], ow[3]);                    \
        *(uint4*)(ab + 16) = make_uint4(ow[4], ow[5], ow[6], ow[7]);                    \
    } while (0)

    float acc[4][8][4];
    #pragma unroll
    for (int i = 0; i < 4; i++)
        #pragma unroll
        for (int j = 0; j < 8; j++)
            #pragma unroll
            for (int q = 0; q < 4; q++) acc[i][j][q] = 0.f;

    ISSUE2B(0); ISSUE2B(1);
    LDG_A(0);
    PREP_STS_A(0, 0);

    const int NC = D_HID / BK;  // 32
    for (int c = 0; c < NC; c++) {
        CP_WAIT1();
        __syncthreads();
        if (c + 2 < NC) ISSUE2B(c + 2); else CP_COMMIT();
        if (c + 1 < NC) LDG_A((c + 1) * BK);
        const char* Ac = smem + OFF2_A + (c & 1) * SA_ST;
        const char* Bc = smem + OFF2_B + (c % 3) * SB_ST;
        COMPUTE_FRAGS(Ac, Bc);
        if (c + 1 < NC) PREP_STS_A((c + 1) & 1, (c + 1) * BK);
    }
    #undef ISSUE2B
    #undef LDG_A
    #undef LN1
    #undef PREP_STS_A

    // ---- epilogue: bias add, scatter to out ----
    const float* b2d = b2 + (size_t)dom * D_OUT + wn * 64;
    #pragma unroll
    for (int mf = 0; mf < 4; mf++) {
        #pragma unroll
        for (int rsel = 0; rsel < 2; rsel++) {
            int r = wm * 64 + mf * 16 + lm + rsel * 8;
            int src = sPerm[r];
            if (src < 0) continue;
            float* orow = out + (size_t)src * D_OUT + wn * 64;
            #pragma unroll
            for (int nf = 0; nf < 8; nf++) {
                int cc = nf * 8 + 2 * lk;
                float v0 = acc[mf][nf][rsel * 2 + 0] + __ldg(b2d + cc);
                float v1 = acc[mf][nf][rsel * 2 + 1] + __ldg(b2d + cc + 1);
                *(float2*)(orow + cc) = make_float2(v0, v1);
            }
        }
    }
}

// ---------------- launch ----------------
extern "C" void kernel_launch(void* const* d_in, const int* in_sizes, int n_in,
                              void* d_out, int out_size) {
    const float* x     = (const float*)d_in[0];
    const int*   dom   = (const int*)  d_in[1];
    const float* W1    = (const float*)d_in[2];
    const float* b1    = (const float*)d_in[3];
    const float* gamma = (const float*)d_in[4];
    const float* beta  = (const float*)d_in[5];
    const float* W2    = (const float*)d_in[6];
    const float* b2    = (const float*)d_in[7];
    float* out = (float*)d_out;

    cudaFuncSetAttribute(gemm1_h, cudaFuncAttributeMaxDynamicSharedMemorySize, SMEM1_TOTAL);
    cudaFuncSetAttribute(gemm2_h, cudaFuncAttributeMaxDynamicSharedMemorySize, SMEM2_TOTAL);

    init_kernel<<<1, 32>>>();
    hist_kernel<<<N_ROWS / 256, 256>>>(dom);
    plan_kernel<<<1, 32>>>();
    scatter_kernel<<<N_ROWS / 256, 256>>>(dom);

    {   // weights: transpose + fp16; x: gather + fp16
        __half* w1h; cudaGetSymbolAddress((void**)&w1h, g_w1h);
        __half* w2h; cudaGetSymbolAddress((void**)&w2h, g_w2h);
        dim3 blk(32, 8);
        dim3 t1(D_HID / 32, D_IN / 32, N_DOM);
        transp_h<<<t1, blk>>>(W1, w1h, D_IN, D_HID);
        dim3 t2(D_OUT / 32, D_HID / 32, N_DOM);
        transp_h<<<t2, blk>>>(W2, w2h, D_HID, D_OUT);
        gather_x_h<<<N_ROWS * 32 / 256, 256>>>(x);
    }

    dim3 grid1(MAX_TILES, D_HID / BN);   // (384, 4)
    gemm1_h<<<grid1, NTHREADS, SMEM1_TOTAL>>>(b1);

    gemm2_h<<<MAX_TILES, NTHREADS, SMEM2_TOTAL>>>(gamma, beta, b2, out);
}

// round 8
// speedup vs baseline: 4.2915x; 1.0805x over previous
#include <cuda_runtime.h>
#include <cuda_fp16.h>
#include <cstdint>

// ---------------- problem constants ----------------
#define N_ROWS   32768
#define D_IN     256
#define D_HID    1024
#define D_OUT    256
#define N_DOM    8
#define LN_EPS   1e-5f

#define BM 128
#define BN 256
#define BK 32
#define NTHREADS 512
#define MAX_TILES 384
#define RSH 80             // smem row stride in BYTES (32 halfs data + 8 pad)

#define SA_ST (BM * RSH)   // 10240 B per A slot
#define SB_ST (BN * RSH)   // 20480 B per B stage

// GEMM1: 2-slot A (register-staged gather+cvt), 3-stage B
#define OFF1_A 0
#define OFF1_B (2 * SA_ST)                        // 20480
#define END1   (OFF1_B + 3 * SB_ST)               // 81920
#define G1_PERM END1
#define G1_STAT (END1 + 512)
#define SMEM1_TOTAL (END1 + 512 + 4096)           // 86528

// GEMM2: 2-slot A (LN loader), 3-stage B
#define OFF2_A 0
#define OFF2_B (2 * SA_ST)                        // 20480
#define END2   (OFF2_B + 3 * SB_ST)               // 81920
#define G2_G    END2
#define G2_B    (END2 + 4096)
#define G2_MU   (END2 + 8192)
#define G2_RS   (END2 + 8704)
#define G2_PERM (END2 + 9216)
#define SMEM2_TOTAL (END2 + 9728)                 // 91648

// ---------------- device scratch ----------------
__device__ int g_count[N_DOM], g_offset[N_DOM], g_fill[N_DOM];
__device__ int g_perm[N_ROWS];
__device__ int g_tile_dom[MAX_TILES], g_tile_row[MAX_TILES], g_tile_cnt[MAX_TILES];
__device__ int g_ntiles;
__device__ __align__(16) __half g_hh[(size_t)N_ROWS * D_HID];     // fp16 h+bias
__device__ __align__(16) float2 g_part[(size_t)N_ROWS * 4];
__device__ __align__(16) __half g_w1h[(size_t)N_DOM * D_HID * D_IN];  // [d][n][k] fp16
__device__ __align__(16) __half g_w2h[(size_t)N_DOM * D_OUT * D_HID]; // [d][n][k] fp16

// ---------------- helpers ----------------
__device__ __forceinline__ void mma16(float* c, const uint32_t* a, const uint32_t* b) {
    asm volatile("mma.sync.aligned.m16n8k16.row.col.f32.f16.f16.f32 "
        "{%0,%1,%2,%3}, {%4,%5,%6,%7}, {%8,%9}, {%0,%1,%2,%3};"
        : "+f"(c[0]), "+f"(c[1]), "+f"(c[2]), "+f"(c[3])
        : "r"(a[0]), "r"(a[1]), "r"(a[2]), "r"(a[3]), "r"(b[0]), "r"(b[1]));
}
#define CP16(dst, src) \
    asm volatile("cp.async.cg.shared.global [%0], [%1], 16;" :: "r"(dst), "l"(src) : "memory")
#define CP_COMMIT() asm volatile("cp.async.commit_group;" ::: "memory")
#define CP_WAIT1()  asm volatile("cp.async.wait_group 1;" ::: "memory")

__device__ __forceinline__ uint32_t pack2(float lo, float hi) {
    __half2 h = __floats2half2_rn(lo, hi);
    return *(uint32_t*)&h;
}

// ---------------- sort/plan kernels ----------------
__global__ void init_kernel() {
    int t = threadIdx.x;
    if (t < N_DOM) { g_count[t] = 0; g_fill[t] = 0; }
}
__global__ void hist_kernel(const int* __restrict__ dom) {
    __shared__ int cnt[N_DOM];
    int t = threadIdx.x;
    if (t < N_DOM) cnt[t] = 0;
    __syncthreads();
    int i = blockIdx.x * blockDim.x + t;
    atomicAdd(&cnt[dom[i]], 1);
    __syncthreads();
    if (t < N_DOM && cnt[t] > 0) atomicAdd(&g_count[t], cnt[t]);
}
__global__ void plan_kernel() {
    if (threadIdx.x == 0 && blockIdx.x == 0) {
        int off = 0, nt = 0;
        for (int d = 0; d < N_DOM; d++) {
            g_offset[d] = off;
            int c = g_count[d];
            for (int t = 0; t < c; t += BM) {
                g_tile_dom[nt] = d;
                g_tile_row[nt] = off + t;
                g_tile_cnt[nt] = min(BM, c - t);
                nt++;
            }
            off += c;
        }
        g_ntiles = nt;
    }
}
__global__ void scatter_kernel(const int* __restrict__ dom) {
    __shared__ int cnt[N_DOM], base[N_DOM];
    int t = threadIdx.x;
    if (t < N_DOM) cnt[t] = 0;
    __syncthreads();
    int i = blockIdx.x * blockDim.x + t;
    int d = dom[i];
    int r = atomicAdd(&cnt[d], 1);
    __syncthreads();
    if (t < N_DOM && cnt[t] > 0) base[t] = atomicAdd(&g_fill[t], cnt[t]);
    __syncthreads();
    g_perm[g_offset[d] + base[d] + r] = i;
}

// ---------------- weight transpose+convert: [z][K][N] f32 -> [z][N][K] fp16 ----------------
__global__ void transp_h(const float* __restrict__ src, __half* __restrict__ dst,
                         int K, int N) {
    __shared__ float t[32][33];
    int z = blockIdx.z;
    const float* s = src + (size_t)z * K * N;
    __half* d = dst + (size_t)z * K * N;
    int n0 = blockIdx.x * 32, k0 = blockIdx.y * 32;
    #pragma unroll
    for (int i = threadIdx.y; i < 32; i += 8)
        t[i][threadIdx.x] = s[(size_t)(k0 + i) * N + n0 + threadIdx.x];
    __syncthreads();
    #pragma unroll
    for (int i = threadIdx.y; i < 32; i += 8)
        d[(size_t)(n0 + i) * K + k0 + threadIdx.x] = __float2half_rn(t[threadIdx.x][i]);
}

// ---------------- fragment compute: 16 warps, warp tile 32x64 (mf=2, nf=8) ----------------
#define COMPUTE_FRAGS(As_, Bs_) do {                                                  \
    _Pragma("unroll")                                                                  \
    for (int kk = 0; kk < BK; kk += 16) {                                              \
        uint32_t a[2][4], b[8][2];                                                     \
        _Pragma("unroll")                                                              \
        for (int mf = 0; mf < 2; mf++) {                                               \
            const char* A_ = (As_) + (wm * 32 + mf * 16 + lm) * RSH + (kk + lk * 2) * 2; \
            a[mf][0] = *(const uint32_t*)(A_);                                         \
            a[mf][1] = *(const uint32_t*)(A_ + 8 * RSH);                               \
            a[mf][2] = *(const uint32_t*)(A_ + 16);                                    \
            a[mf][3] = *(const uint32_t*)(A_ + 8 * RSH + 16);                          \
        }                                                                              \
        _Pragma("unroll")                                                              \
        for (int nf = 0; nf < 8; nf++) {                                               \
            const char* B_ = (Bs_) + (wn * 64 + nf * 8 + lm) * RSH + (kk + lk * 2) * 2; \
            b[nf][0] = *(const uint32_t*)(B_);                                         \
            b[nf][1] = *(const uint32_t*)(B_ + 16);                                    \
        }                                                                              \
        _Pragma("unroll")                                                              \
        for (int mf = 0; mf < 2; mf++)                                                 \
            _Pragma("unroll")                                                          \
            for (int nf = 0; nf < 8; nf++)                                             \
                mma16(acc[mf][nf], a[mf], b[nf]);                                      \
    }                                                                                  \
} while (0)

// ============================================================================
// GEMM1: h = fp16(x[perm]) @ W1h[d]^T + b1 -> g_hh; per-row (sum,sumsq)
// 512 threads; A: fused gather+cvt (2-slot); B: 3-stage cp.async
// ============================================================================
__global__ __launch_bounds__(NTHREADS, 1)
void gemm1_h(const float* __restrict__ x,
             const float* __restrict__ b1) {
    extern __shared__ __align__(16) char smem[];
    uint32_t sbase = (uint32_t)__cvta_generic_to_shared(smem);
    int*    sPerm = (int*)(smem + G1_PERM);
    float2* sStat = (float2*)(smem + G1_STAT);

    int bt = blockIdx.x;
    if (bt >= g_ntiles) return;
    int dom  = g_tile_dom[bt];
    int row0 = g_tile_row[bt];
    int cnt  = g_tile_cnt[bt];
    int by   = blockIdx.y;
    int colBase = by * BN;

    int tid  = threadIdx.x;
    int lane = tid & 31, wid = tid >> 5;
    int wm = wid >> 2, wn = wid & 3;
    int lk = lane & 3, lm = lane >> 2;

    if (tid < BM) sPerm[tid] = (tid < cnt) ? g_perm[row0 + tid] : -1;
    __syncthreads();

    const __half* W1h = g_w1h + ((size_t)dom * D_HID + colBase) * D_IN;

    // A loader: row = tid>>2 (0..127), seg = tid&3 (8 floats -> 8 halfs)
    int arow = tid >> 2, aseg = tid & 3;
    int asrc = sPerm[arow];
    // B loader: n = tid>>1 (0..255), half of 64B row
    int bn = tid >> 1, bj = tid & 1;

    #define ISSUE1B(cidx) do {                                                         \
        int k0_ = (cidx) * BK;                                                         \
        uint32_t sb = sbase + OFF1_B + ((cidx) % 3) * SB_ST;                           \
        const __half* bsrc = W1h + (size_t)bn * D_IN + k0_ + bj * 16;                  \
        CP16(sb + bn * RSH + bj * 32,      bsrc);                                      \
        CP16(sb + bn * RSH + bj * 32 + 16, bsrc + 8);                                  \
        CP_COMMIT();                                                                   \
    } while (0)

    float4 xv0, xv1;
    #define LDG_A1(k0_) do {                                                           \
        if (asrc >= 0) {                                                               \
            const float* sp = x + (size_t)asrc * D_IN + (k0_) + aseg * 8;              \
            xv0 = *(const float4*)(sp);                                                \
            xv1 = *(const float4*)(sp + 4);                                            \
        } else {                                                                       \
            xv0 = make_float4(0.f, 0.f, 0.f, 0.f);                                     \
            xv1 = xv0;                                                                 \
        }                                                                              \
    } while (0)

    #define PREP_STS_A1(slot) do {                                                     \
        uint4 o;                                                                       \
        o.x = pack2(xv0.x, xv0.y); o.y = pack2(xv0.z, xv0.w);                          \
        o.z = pack2(xv1.x, xv1.y); o.w = pack2(xv1.z, xv1.w);                          \
        *(uint4*)(smem + OFF1_A + (slot) * SA_ST + arow * RSH + aseg * 16) = o;        \
    } while (0)

    float acc[2][8][4];
    #pragma unroll
    for (int i = 0; i < 2; i++)
        #pragma unroll
        for (int j = 0; j < 8; j++)
            #pragma unroll
            for (int q = 0; q < 4; q++) acc[i][j][q] = 0.f;

    ISSUE1B(0); ISSUE1B(1);
    LDG_A1(0);
    PREP_STS_A1(0);

    const int NC = D_IN / BK;  // 8
    for (int c = 0; c < NC; c++) {
        CP_WAIT1();
        __syncthreads();
        if (c + 2 < NC) ISSUE1B(c + 2); else CP_COMMIT();
        if (c + 1 < NC) LDG_A1((c + 1) * BK);
        const char* Ac = smem + OFF1_A + (c & 1) * SA_ST;
        const char* Bc = smem + OFF1_B + (c % 3) * SB_ST;
        COMPUTE_FRAGS(Ac, Bc);
        if (c + 1 < NC) PREP_STS_A1((c + 1) & 1);
    }
    #undef ISSUE1B
    #undef LDG_A1
    #undef PREP_STS_A1

    // ---- epilogue: bias add, store fp16 h, per-row stats ----
    __syncthreads();
    const float* b1d = b1 + (size_t)dom * D_HID + colBase + wn * 64;
    #pragma unroll
    for (int mf = 0; mf < 2; mf++) {
        #pragma unroll
        for (int rsel = 0; rsel < 2; rsel++) {
            int r = wm * 32 + mf * 16 + lm + rsel * 8;
            float s = 0.f, ss = 0.f;
            __half* hrow = g_hh + (size_t)(row0 + r) * D_HID + colBase + wn * 64;
            bool wr = (r < cnt);
            #pragma unroll
            for (int nf = 0; nf < 8; nf++) {
                int cc = nf * 8 + 2 * lk;
                float v0 = acc[mf][nf][rsel * 2 + 0] + __ldg(b1d + cc);
                float v1 = acc[mf][nf][rsel * 2 + 1] + __ldg(b1d + cc + 1);
                s += v0 + v1;
                ss += v0 * v0 + v1 * v1;
                if (wr) *(uint32_t*)(hrow + cc) = pack2(v0, v1);
            }
            s  += __shfl_xor_sync(0xffffffffu, s, 1);
            s  += __shfl_xor_sync(0xffffffffu, s, 2);
            ss += __shfl_xor_sync(0xffffffffu, ss, 1);
            ss += __shfl_xor_sync(0xffffffffu, ss, 2);
            if (lk == 0) sStat[r * 4 + wn] = make_float2(s, ss);
        }
    }
    __syncthreads();
    if (tid < BM && tid < cnt) {
        float s = 0.f, ss = 0.f;
        #pragma unroll
        for (int q = 0; q < 4; q++) {
            float2 p = sStat[tid * 4 + q];
            s += p.x; ss += p.y;
        }
        g_part[(size_t)(row0 + tid) * 4 + by] = make_float2(s, ss);
    }
}

// ============================================================================
// GEMM2: out[perm] = relu(LN(h)*gamma+beta) @ W2h[d]^T + b2
// 512 threads; A: fused LN loader (2-slot); B: 3-stage cp.async
// ============================================================================
__global__ __launch_bounds__(NTHREADS, 1)
void gemm2_h(const float* __restrict__ gamma,
             const float* __restrict__ beta,
             const float* __restrict__ b2,
             float* __restrict__ out) {
    extern __shared__ __align__(16) char smem[];
    uint32_t sbase = (uint32_t)__cvta_generic_to_shared(smem);
    float* sG  = (float*)(smem + G2_G);
    float* sBt = (float*)(smem + G2_B);
    float* sMu = (float*)(smem + G2_MU);
    float* sRs = (float*)(smem + G2_RS);
    int*   sPerm = (int*)(smem + G2_PERM);

    int bt = blockIdx.x;
    if (bt >= g_ntiles) return;
    int dom  = g_tile_dom[bt];
    int row0 = g_tile_row[bt];
    int cnt  = g_tile_cnt[bt];

    int tid  = threadIdx.x;
    int lane = tid & 31, wid = tid >> 5;
    int wm = wid >> 2, wn = wid & 3;
    int lk = lane & 3, lm = lane >> 2;

    for (int i = tid; i < D_HID; i += NTHREADS) {
        sG[i]  = gamma[(size_t)dom * D_HID + i];
        sBt[i] = beta[(size_t)dom * D_HID + i];
    }
    if (tid < BM) {
        sPerm[tid] = (tid < cnt) ? g_perm[row0 + tid] : -1;
        float mu = 0.f, rs = 0.f;
        if (tid < cnt) {
            float s = 0.f, ss = 0.f;
            #pragma unroll
            for (int q = 0; q < 4; q++) {
                float2 p = g_part[(size_t)(row0 + tid) * 4 + q];
                s += p.x; ss += p.y;
            }
            mu = s * (1.f / D_HID);
            float var = ss * (1.f / D_HID) - mu * mu;
            rs = rsqrtf(var + LN_EPS);
        }
        sMu[tid] = mu; sRs[tid] = rs;
    }
    __syncthreads();

    const __half* W2h = g_w2h + (size_t)dom * D_OUT * D_HID;

    // A loader: row = tid>>2, 8 halfs at (tid&3)*8
    int arow = tid >> 2, aseg = tid & 3;
    int icl = min(arow, cnt - 1);
    int iar = row0 + icl;
    float amu = sMu[icl], ars = sRs[icl];
    // B loader: n = tid>>1, half of 64B row
    int bn = tid >> 1, bj = tid & 1;

    #define ISSUE2B(cidx) do {                                                         \
        int k0_ = (cidx) * BK;                                                         \
        uint32_t sb = sbase + OFF2_B + ((cidx) % 3) * SB_ST;                           \
        const __half* bsrc = W2h + (size_t)bn * D_HID + k0_ + bj * 16;                 \
        CP16(sb + bn * RSH + bj * 32,      bsrc);                                      \
        CP16(sb + bn * RSH + bj * 32 + 16, bsrc + 8);                                  \
        CP_COMMIT();                                                                   \
    } while (0)

    uint4 hv;
    #define LDG_A2(k0_) do {                                                           \
        hv = *(const uint4*)(g_hh + (size_t)iar * D_HID + (k0_) + aseg * 8);           \
    } while (0)

    #define LN1(f, kb) fmaxf(fmaf(((f) - amu) * ars, sG[kb], sBt[kb]), 0.f)

    #define PREP_STS_A2(slot, k0_) do {                                                \
        int kb = (k0_) + aseg * 8;                                                     \
        uint32_t hw[4] = {hv.x, hv.y, hv.z, hv.w};                                     \
        uint32_t ow[4];                                                                \
        _Pragma("unroll")                                                              \
        for (int j_ = 0; j_ < 4; j_++) {                                               \
            float2 f = __half22float2(*(__half2*)&hw[j_]);                             \
            ow[j_] = pack2(LN1(f.x, kb + 2 * j_), LN1(f.y, kb + 2 * j_ + 1));          \
        }                                                                              \
        *(uint4*)(smem + OFF2_A + (slot) * SA_ST + arow * RSH + aseg * 16) =           \
            make_uint4(ow[0], ow[1], ow[2], ow[3]);                                    \
    } while (0)

    float acc[2][8][4];
    #pragma unroll
    for (int i = 0; i < 2; i++)
        #pragma unroll
        for (int j = 0; j < 8; j++)
            #pragma unroll
            for (int q = 0; q < 4; q++) acc[i][j][q] = 0.f;

    ISSUE2B(0); ISSUE2B(1);
    LDG_A2(0);
    PREP_STS_A2(0, 0);

    const int NC = D_HID / BK;  // 32
    for (int c = 0; c < NC; c++) {
        CP_WAIT1();
        __syncthreads();
        if (c + 2 < NC) ISSUE2B(c + 2); else CP_COMMIT();
        if (c + 1 < NC) LDG_A2((c + 1) * BK);
        const char* Ac = smem + OFF2_A + (c & 1) * SA_ST;
        const char* Bc = smem + OFF2_B + (c % 3) * SB_ST;
        COMPUTE_FRAGS(Ac, Bc);
        if (c + 1 < NC) PREP_STS_A2((c + 1) & 1, (c + 1) * BK);
    }
    #undef ISSUE2B
    #undef LDG_A2
    #undef LN1
    #undef PREP_STS_A2

    // ---- epilogue: bias add, scatter to out ----
    const float* b2d = b2 + (size_t)dom * D_OUT + wn * 64;
    #pragma unroll
    for (int mf = 0; mf < 2; mf++) {
        #pragma unroll
        for (int rsel = 0; rsel < 2; rsel++) {
            int r = wm * 32 + mf * 16 + lm + rsel * 8;
            int src = sPerm[r];
            if (src < 0) continue;
            float* orow = out + (size_t)src * D_OUT + wn * 64;
            #pragma unroll
            for (int nf = 0; nf < 8; nf++) {
                int cc = nf * 8 + 2 * lk;
                float v0 = acc[mf][nf][rsel * 2 + 0] + __ldg(b2d + cc);
                float v1 = acc[mf][nf][rsel * 2 + 1] + __ldg(b2d + cc + 1);
                *(float2*)(orow + cc) = make_float2(v0, v1);
            }
        }
    }
}

// ---------------- launch ----------------
extern "C" void kernel_launch(void* const* d_in, const int* in_sizes, int n_in,
                              void* d_out, int out_size) {
    const float* x     = (const float*)d_in[0];
    const int*   dom   = (const int*)  d_in[1];
    const float* W1    = (const float*)d_in[2];
    const float* b1    = (const float*)d_in[3];
    const float* gamma = (const float*)d_in[4];
    const float* beta  = (const float*)d_in[5];
    const float* W2    = (const float*)d_in[6];
    const float* b2    = (const float*)d_in[7];
    float* out = (float*)d_out;

    cudaFuncSetAttribute(gemm1_h, cudaFuncAttributeMaxDynamicSharedMemorySize, SMEM1_TOTAL);
    cudaFuncSetAttribute(gemm2_h, cudaFuncAttributeMaxDynamicSharedMemorySize, SMEM2_TOTAL);

    init_kernel<<<1, 32>>>();
    hist_kernel<<<N_ROWS / 256, 256>>>(dom);
    plan_kernel<<<1, 32>>>();
    scatter_kernel<<<N_ROWS / 256, 256>>>(dom);

    {   // weights: transpose + fp16
        __half* w1h; cudaGetSymbolAddress((void**)&w1h, g_w1h);
        __half* w2h; cudaGetSymbolAddress((void**)&w2h, g_w2h);
        dim3 blk(32, 8);
        dim3 t1(D_HID / 32, D_IN / 32, N_DOM);
        transp_h<<<t1, blk>>>(W1, w1h, D_IN, D_HID);
        dim3 t2(D_OUT / 32, D_HID / 32, N_DOM);
        transp_h<<<t2, blk>>>(W2, w2h, D_HID, D_OUT);
    }

    dim3 grid1(MAX_TILES, D_HID / BN);   // (384, 4)
    gemm1_h<<<grid1, NTHREADS, SMEM1_TOTAL>>>(x, b1);

    gemm2_h<<<MAX_TILES, NTHREADS, SMEM2_TOTAL>>>(gamma, beta, b2, out);
}